// round 14
// baseline (speedup 1.0000x reference)
#include <cuda_runtime.h>
#include <cuda_bf16.h>
#include <math.h>
#include <stdint.h>

// ---------------- problem constants ----------------
#define BATCH 2
#define LSEQ 4096
#define DMOD 2048
#define D3 6144
#define FORD 64
#define FFT_N 8192
#define FFT_HN 4096
#define FFT_T 512

// bf16x3 split GEMM (used for out_proj): packed [hi | lo], schedule A{hi,lo,hi} x B{hi,hi,lo}
#define KPACK 4096
#define KS2 6144
#define BM 128
#define BN 128
#define BK 64
#define NCHUNK (KS2 / BK)          // 96
#define STAGE 32768
#define NSTAGE 3
#define GEMM_SMEM (NSTAGE * STAGE) // 96KB -> 2 CTAs/SM
#define GEMM_T 128
#define SUPER_M 16

// int8 dual-digit GEMM (used for in_proj): rows [q1 | q2], a = s*(q1 + q2/254)
#define KPQ 4096                   // bytes per packed row
#define BKQ 128                    // bytes per chunk
#define QSTAGE 32768               // A 16KB + B 16KB
#define QSMEM (NSTAGE * QSTAGE)    // 96KB
#define CROSS_INV (1.0f / 254.0f)

// ---------------- device scratch ----------------
__device__ float  g_U[(size_t)BATCH * D3 * LSEQ];
__device__ float  g_H[(size_t)LSEQ * FORD];
__device__ float  g_Kt[(size_t)DMOD * LSEQ];
__device__ float2 g_Kf[(size_t)DMOD * FFT_N];
__device__ float  g_YG[(size_t)BATCH * DMOD * LSEQ];
__device__ float2 g_TW[FFT_HN];
__device__ int8_t g_A1q[(size_t)BATCH * LSEQ * KPQ];   // x quantized (8192, 4096B)
__device__ int8_t g_B1q[(size_t)D3 * KPQ];             // in_w quantized
__device__ float  g_SA1[BATCH * LSEQ];
__device__ float  g_SB1[D3];
__device__ float  g_Ctmp[(size_t)BATCH * LSEQ * D3];   // cross-term accumulator (fp32)
__device__ __nv_bfloat16 g_B2[(size_t)DMOD * KPACK];   // out_w bf16 [hi|lo]
__device__ __nv_bfloat16 g_A2[(size_t)BATCH * LSEQ * KPACK];

// ---------------- PTX helpers (baseline ISA only) ----------------
__device__ __forceinline__ uint32_t smem_to_u32(const void* p) {
    uint32_t a;
    asm("{ .reg .u64 t; cvta.to.shared.u64 t, %1; cvt.u32.u64 %0, t; }" : "=r"(a) : "l"(p));
    return a;
}
#define SWZ(o) ((o) ^ (((o) >> 3) & 0x70))

#define CP_ASYNC16(dst, src) \
    asm volatile("cp.async.cg.shared.global [%0], [%1], 16;" :: "r"(dst), "l"(src))
#define CP_COMMIT() asm volatile("cp.async.commit_group;" ::: "memory")
#define CP_WAIT1()  asm volatile("cp.async.wait_group 1;" ::: "memory")

#define LDSM_X4(r0, r1, r2, r3, addr)                                         \
    asm volatile("ldmatrix.sync.aligned.m8n8.x4.shared.b16 {%0,%1,%2,%3}, [%4];" \
                 : "=r"(r0), "=r"(r1), "=r"(r2), "=r"(r3) : "r"(addr))

#define MMA16816(c, a, b)                                                     \
    asm volatile("mma.sync.aligned.m16n8k16.row.col.f32.bf16.bf16.f32 "       \
                 "{%0,%1,%2,%3}, {%4,%5,%6,%7}, {%8,%9}, {%0,%1,%2,%3};"      \
                 : "+f"((c)[0]), "+f"((c)[1]), "+f"((c)[2]), "+f"((c)[3])     \
                 : "r"((a)[0]), "r"((a)[1]), "r"((a)[2]), "r"((a)[3]),        \
                   "r"((b)[0]), "r"((b)[1]))

#define MMA16832S8(c, a, b)                                                   \
    asm volatile("mma.sync.aligned.m16n8k32.row.col.s32.s8.s8.s32 "           \
                 "{%0,%1,%2,%3}, {%4,%5,%6,%7}, {%8,%9}, {%0,%1,%2,%3};"      \
                 : "+r"((c)[0]), "+r"((c)[1]), "+r"((c)[2]), "+r"((c)[3])     \
                 : "r"((a)[0]), "r"((a)[1]), "r"((a)[2]), "r"((a)[3]),        \
                   "r"((b)[0]), "r"((b)[1]))

// ---------------- complex helpers ----------------
__device__ __forceinline__ float2 cadd(float2 a, float2 b) { return make_float2(a.x + b.x, a.y + b.y); }
__device__ __forceinline__ float2 csub(float2 a, float2 b) { return make_float2(a.x - b.x, a.y - b.y); }
__device__ __forceinline__ float2 cmul(float2 a, float2 b) {
    return make_float2(a.x * b.x - a.y * b.y, a.x * b.y + a.y * b.x);
}
__device__ __forceinline__ float2 cmulc(float2 a, float2 b) {
    return make_float2(a.x * b.x + a.y * b.y, a.y * b.x - a.x * b.y);
}

// ---------------- int8 row quantizer: fp32 (rows,2048) -> [q1|q2] + scale ----------------
__global__ void quant_rows_kernel(const float* __restrict__ src,
                                  int8_t* __restrict__ dst, float* __restrict__ scales)
{
    __shared__ float red[256];
    const int row = blockIdx.x;
    const int tid = threadIdx.x;
    const float4* s4 = (const float4*)(src + (size_t)row * 2048);
    float m = 0.f;
    for (int k = tid; k < 512; k += 256) {
        float4 v = s4[k];
        m = fmaxf(m, fmaxf(fmaxf(fabsf(v.x), fabsf(v.y)), fmaxf(fabsf(v.z), fabsf(v.w))));
    }
    red[tid] = m;
    __syncthreads();
    for (int st = 128; st; st >>= 1) {
        if (tid < st) red[tid] = fmaxf(red[tid], red[tid + st]);
        __syncthreads();
    }
    const float mx = red[0];
    const float scv = (mx > 0.f) ? mx / 127.f : 1.f;
    const float inv = (mx > 0.f) ? 127.f / mx : 0.f;
    if (tid == 0) scales[row] = scv;
    char4* d1 = (char4*)(dst + (size_t)row * KPQ);
    char4* d2 = (char4*)(dst + (size_t)row * KPQ + 2048);
    for (int k = tid; k < 512; k += 256) {
        float4 v = s4[k];
        float q[4], r[4], q2[4];
        float f[4] = {v.x, v.y, v.z, v.w};
#pragma unroll
        for (int j = 0; j < 4; ++j) {
            q[j] = fminf(fmaxf(rintf(f[j] * inv), -127.f), 127.f);
            r[j] = f[j] - q[j] * scv;
            q2[j] = fminf(fmaxf(rintf(r[j] * inv * 254.f), -127.f), 127.f);
        }
        d1[k] = make_char4((signed char)q[0], (signed char)q[1], (signed char)q[2], (signed char)q[3]);
        d2[k] = make_char4((signed char)q2[0], (signed char)q2[1], (signed char)q2[2], (signed char)q2[3]);
    }
}

// ---------------- bf16 split converter (for out_proj weight) ----------------
__global__ void convert_split_kernel(const float* __restrict__ src,
                                     __nv_bfloat16* __restrict__ dst, size_t total4)
{
    size_t i = (size_t)blockIdx.x * blockDim.x + threadIdx.x;
    if (i >= total4) return;
    float4 v = ((const float4*)src)[i];
    size_t e = i * 4;
    size_t r = e >> 11;
    int k = (int)(e & 2047);
    float f[4] = {v.x, v.y, v.z, v.w};
    __nv_bfloat16 h[4], l[4];
#pragma unroll
    for (int j = 0; j < 4; ++j) {
        h[j] = __float2bfloat16(f[j]);
        l[j] = __float2bfloat16(f[j] - __bfloat162float(h[j]));
    }
    __nv_bfloat16* base = dst + r * KPACK + k;
    *(__nv_bfloat162*)(base)            = __nv_bfloat162(h[0], h[1]);
    *(__nv_bfloat162*)(base + 2)        = __nv_bfloat162(h[2], h[3]);
    *(__nv_bfloat162*)(base + 2048)     = __nv_bfloat162(l[0], l[1]);
    *(__nv_bfloat162*)(base + 2048 + 2) = __nv_bfloat162(l[2], l[3]);
}

// YG (B,D,L) -> A2 (b*L+l, [hi|lo]) via 32x32 smem transpose
__global__ void yg_convert_kernel(const float* __restrict__ YG, __nv_bfloat16* __restrict__ A2)
{
    __shared__ float tile[32][33];
    const int b = blockIdx.z;
    const int d0 = blockIdx.y * 32;
    const int l0 = blockIdx.x * 32;
    const int tx = threadIdx.x, ty = threadIdx.y;
    for (int i = ty; i < 32; i += 8)
        tile[i][tx] = YG[((size_t)b * DMOD + d0 + i) * LSEQ + l0 + tx];
    __syncthreads();
    for (int i = ty; i < 32; i += 8) {
        float v = tile[tx][i];
        __nv_bfloat16 h = __float2bfloat16(v);
        __nv_bfloat16 l = __float2bfloat16(v - __bfloat162float(h));
        size_t m = (size_t)b * LSEQ + l0 + i;
        A2[m * KPACK + d0 + tx]        = h;
        A2[m * KPACK + 2048 + d0 + tx] = l;
    }
}

// ================= int8 GEMM (in_proj) =================
// PHASE 0 (cross): K=4096 packed {q1*p2, q2*p1} -> Ctmp = acc/254
// PHASE 1 (main):  K=2048 {q1*p1}; epilogue out = sa*sb*(acc + Ctmp) + bias, transposed into U
__device__ __forceinline__ int mapAq(int phase, int c) {
    return (phase == 0) ? ((c < 16) ? c * BKQ : 2048 + (c - 16) * BKQ) : c * BKQ;
}
__device__ __forceinline__ int mapBq(int phase, int c) {
    return (phase == 0) ? ((c < 16) ? 2048 + c * BKQ : (c - 16) * BKQ) : c * BKQ;
}

__device__ __forceinline__ void load_stage_q(uint32_t sA, uint32_t sB,
                                             const int8_t* __restrict__ A,
                                             const int8_t* __restrict__ Bm,
                                             int m0, int n0, int kA, int kB, int tid)
{
#pragma unroll
    for (int i = 0; i < 8; ++i) {
        int g = tid + i * GEMM_T;
        int row = g >> 3, seg = g & 7;
        const void* gp = A + (size_t)(m0 + row) * KPQ + kA + seg * 16;
        uint32_t off = (uint32_t)(row * 128 + seg * 16);
        CP_ASYNC16(sA + SWZ(off), gp);
    }
#pragma unroll
    for (int i = 0; i < 8; ++i) {
        int g = tid + i * GEMM_T;
        int row = g >> 3, seg = g & 7;
        const void* gp = Bm + (size_t)(n0 + row) * KPQ + kB + seg * 16;
        uint32_t off = (uint32_t)(row * 128 + seg * 16);
        CP_ASYNC16(sB + SWZ(off), gp);
    }
}

__device__ __forceinline__ void compute_chunk_q(uint32_t sA, uint32_t sB,
                                                int lane, int wm, int wn,
                                                int acc[4][8][4])
{
    const int rlow = lane & 15;
    const int khalf = (lane >> 4) * 16;
#pragma unroll
    for (int kk = 0; kk < 4; ++kk) {
        const int kb = kk * 32 + khalf;       // byte offset within 128B row
        uint32_t af[4][4], bf[8][2];
#pragma unroll
        for (int mt = 0; mt < 4; ++mt) {
            uint32_t off = (uint32_t)((wm * 64 + mt * 16 + rlow) * 128 + kb);
            LDSM_X4(af[mt][0], af[mt][1], af[mt][2], af[mt][3], sA + SWZ(off));
        }
#pragma unroll
        for (int nb = 0; nb < 4; ++nb) {
            uint32_t r0, r1, r2, r3;
            uint32_t off = (uint32_t)((wn * 64 + nb * 16 + rlow) * 128 + kb);
            LDSM_X4(r0, r1, r2, r3, sB + SWZ(off));
            bf[nb * 2][0] = r0; bf[nb * 2][1] = r2;
            bf[nb * 2 + 1][0] = r1; bf[nb * 2 + 1][1] = r3;
        }
#pragma unroll
        for (int mt = 0; mt < 4; ++mt)
#pragma unroll
            for (int nf = 0; nf < 8; ++nf)
                MMA16832S8(acc[mt][nf], af[mt], bf[nf]);
    }
}

template <int PHASE>
__global__ __launch_bounds__(GEMM_T, 2) void imma_gemm_kernel(
    const int8_t* __restrict__ A, const int8_t* __restrict__ Bm,
    const float* __restrict__ sa, const float* __restrict__ sb,
    const float* __restrict__ bias, float* __restrict__ ctmp,
    float* __restrict__ out, int Ntot)
{
    extern __shared__ char smem[];
    const uint32_t sbase = smem_to_u32(smem);
    const int tid = threadIdx.x;
    const int lane = tid & 31, wid = tid >> 5;
    const int wm = wid >> 1, wn = wid & 1;

    int bid = blockIdx.y * gridDim.x + blockIdx.x;
    int per = SUPER_M * gridDim.x;
    int sup = bid / per, rem = bid % per;
    const int m0 = (sup * SUPER_M + (rem & (SUPER_M - 1))) * BM;
    const int n0 = (rem / SUPER_M) * BN;

    const int nch = (PHASE == 0) ? 32 : 16;

    int acc[4][8][4];
#pragma unroll
    for (int a = 0; a < 4; ++a)
#pragma unroll
        for (int b = 0; b < 8; ++b)
#pragma unroll
            for (int c = 0; c < 4; ++c) acc[a][b][c] = 0;

    load_stage_q(sbase, sbase + 16384, A, Bm, m0, n0, mapAq(PHASE, 0), mapBq(PHASE, 0), tid);
    CP_COMMIT();
    load_stage_q(sbase + QSTAGE, sbase + QSTAGE + 16384, A, Bm, m0, n0,
                 mapAq(PHASE, 1), mapBq(PHASE, 1), tid);
    CP_COMMIT();

    for (int c = 0; c < nch; ++c) {
        CP_WAIT1();
        __syncthreads();
        if (c + 2 < nch) {
            int st = (c + 2) % NSTAGE;
            load_stage_q(sbase + st * QSTAGE, sbase + st * QSTAGE + 16384,
                         A, Bm, m0, n0, mapAq(PHASE, c + 2), mapBq(PHASE, c + 2), tid);
        }
        CP_COMMIT();
        int st = c % NSTAGE;
        compute_chunk_q(sbase + st * QSTAGE, sbase + st * QSTAGE + 16384, lane, wm, wn, acc);
    }
    __syncthreads();

    if (PHASE == 0) {
        // write cross accumulator, pre-scaled by 1/254
        const int mw = m0 + wm * 64, nw = n0 + wn * 64;
#pragma unroll
        for (int mt = 0; mt < 4; ++mt) {
            int row = mw + mt * 16 + (lane >> 2);
#pragma unroll
            for (int nf = 0; nf < 8; ++nf) {
                int col = nw + nf * 8 + (lane & 3) * 2;
                float2 v0 = make_float2((float)acc[mt][nf][0] * CROSS_INV,
                                        (float)acc[mt][nf][1] * CROSS_INV);
                float2 v1 = make_float2((float)acc[mt][nf][2] * CROSS_INV,
                                        (float)acc[mt][nf][3] * CROSS_INV);
                *(float2*)&ctmp[(size_t)row * Ntot + col] = v0;
                *(float2*)&ctmp[(size_t)(row + 8) * Ntot + col] = v1;
            }
        }
    } else {
        // main phase: combine with ctmp, scale, stage transposed, write into U (B,3D,L)
        float (*sc)[132] = (float(*)[132])smem;
#pragma unroll
        for (int mt = 0; mt < 4; ++mt) {
            int r0 = wm * 64 + mt * 16 + (lane >> 2);
            int r1 = r0 + 8;
            float sa0 = sa[m0 + r0], sa1 = sa[m0 + r1];
#pragma unroll
            for (int nf = 0; nf < 8; ++nf) {
                int nl = wn * 64 + nf * 8 + (lane & 3) * 2;
                float sb0 = sb[n0 + nl], sb1 = sb[n0 + nl + 1];
                float2 ct0 = *(const float2*)&ctmp[(size_t)(m0 + r0) * Ntot + n0 + nl];
                float2 ct1 = *(const float2*)&ctmp[(size_t)(m0 + r1) * Ntot + n0 + nl];
                sc[nl][r0]     = sa0 * sb0 * ((float)acc[mt][nf][0] + ct0.x);
                sc[nl + 1][r0] = sa0 * sb1 * ((float)acc[mt][nf][1] + ct0.y);
                sc[nl][r1]     = sa1 * sb0 * ((float)acc[mt][nf][2] + ct1.x);
                sc[nl + 1][r1] = sa1 * sb1 * ((float)acc[mt][nf][3] + ct1.y);
            }
        }
        __syncthreads();
        const int b = m0 >> 12;
        const int lbase = m0 & (LSEQ - 1);
        const int n = tid;
        const float bb = bias[n0 + n];
        float* dst = out + ((size_t)b * D3 + n0 + n) * LSEQ + lbase;
        const float* srow = &sc[n][0];
#pragma unroll
        for (int i = 0; i < 32; ++i) {
            float4 v = *(const float4*)(srow + i * 4);
            v.x += bb; v.y += bb; v.z += bb; v.w += bb;
            *(float4*)(dst + i * 4) = v;
        }
    }
}

// ================= bf16x3 GEMM (out_proj) =================
__device__ __forceinline__ void load_stage(uint32_t sA, uint32_t sB,
                                           const __nv_bfloat16* __restrict__ A,
                                           const __nv_bfloat16* __restrict__ Bm,
                                           int m0, int n0, int kA, int kB, int tid)
{
#pragma unroll
    for (int i = 0; i < 8; ++i) {
        int g = tid + i * GEMM_T;
        int row = g >> 3, seg = g & 7;
        const void* gp = A + (size_t)(m0 + row) * KPACK + kA + seg * 8;
        uint32_t off = (uint32_t)(row * 128 + seg * 16);
        CP_ASYNC16(sA + SWZ(off), gp);
    }
#pragma unroll
    for (int i = 0; i < 8; ++i) {
        int g = tid + i * GEMM_T;
        int row = g >> 3, seg = g & 7;
        const void* gp = Bm + (size_t)(n0 + row) * KPACK + kB + seg * 8;
        uint32_t off = (uint32_t)(row * 128 + seg * 16);
        CP_ASYNC16(sB + SWZ(off), gp);
    }
}

__device__ __forceinline__ void compute_chunk(uint32_t sA, uint32_t sB,
                                              int lane, int wm, int wn,
                                              float acc[4][8][4])
{
    const int rlow = lane & 15;
    const int khalf = (lane >> 4) * 16;
#pragma unroll
    for (int kk = 0; kk < 4; ++kk) {
        const int kb = kk * 32 + khalf;
        uint32_t af[4][4], bf[8][2];
#pragma unroll
        for (int mt = 0; mt < 4; ++mt) {
            uint32_t off = (uint32_t)((wm * 64 + mt * 16 + rlow) * 128 + kb);
            LDSM_X4(af[mt][0], af[mt][1], af[mt][2], af[mt][3], sA + SWZ(off));
        }
#pragma unroll
        for (int nb = 0; nb < 4; ++nb) {
            uint32_t r0, r1, r2, r3;
            uint32_t off = (uint32_t)((wn * 64 + nb * 16 + rlow) * 128 + kb);
            LDSM_X4(r0, r1, r2, r3, sB + SWZ(off));
            bf[nb * 2][0] = r0; bf[nb * 2][1] = r2;
            bf[nb * 2 + 1][0] = r1; bf[nb * 2 + 1][1] = r3;
        }
#pragma unroll
        for (int mt = 0; mt < 4; ++mt)
#pragma unroll
            for (int nf = 0; nf < 8; ++nf)
                MMA16816(acc[mt][nf], af[mt], bf[nf]);
    }
}

__device__ __forceinline__ int mapA(int k0) { int s = k0 >> 11; return ((s & 1) << 11) + (k0 & 2047); }
__device__ __forceinline__ int mapB(int k0) { int s = k0 >> 11; return ((s >> 1) << 11) + (k0 & 2047); }

__global__ __launch_bounds__(GEMM_T, 2) void mma_gemm_kernel(
    const __nv_bfloat16* __restrict__ A, const __nv_bfloat16* __restrict__ Bm,
    const float* __restrict__ bias, float* __restrict__ out, int Ntot)
{
    extern __shared__ char smem[];
    const uint32_t sbase = smem_to_u32(smem);
    const int tid = threadIdx.x;
    const int lane = tid & 31, wid = tid >> 5;
    const int wm = wid >> 1, wn = wid & 1;

    int bid = blockIdx.y * gridDim.x + blockIdx.x;
    int per = SUPER_M * gridDim.x;
    int sup = bid / per, rem = bid % per;
    const int m0 = (sup * SUPER_M + (rem & (SUPER_M - 1))) * BM;
    const int n0 = (rem / SUPER_M) * BN;

    float acc[4][8][4];
#pragma unroll
    for (int a = 0; a < 4; ++a)
#pragma unroll
        for (int b = 0; b < 8; ++b)
#pragma unroll
            for (int c = 0; c < 4; ++c) acc[a][b][c] = 0.f;

    load_stage(sbase, sbase + 16384, A, Bm, m0, n0, mapA(0), mapB(0), tid);
    CP_COMMIT();
    load_stage(sbase + STAGE, sbase + STAGE + 16384, A, Bm, m0, n0, mapA(BK), mapB(BK), tid);
    CP_COMMIT();

    for (int c = 0; c < NCHUNK; ++c) {
        CP_WAIT1();
        __syncthreads();
        if (c + 2 < NCHUNK) {
            int st = (c + 2) % NSTAGE;
            int k0 = (c + 2) * BK;
            load_stage(sbase + st * STAGE, sbase + st * STAGE + 16384,
                       A, Bm, m0, n0, mapA(k0), mapB(k0), tid);
        }
        CP_COMMIT();
        int st = c % NSTAGE;
        compute_chunk(sbase + st * STAGE, sbase + st * STAGE + 16384, lane, wm, wn, acc);
    }
    __syncthreads();

    const int mw = m0 + wm * 64, nw = n0 + wn * 64;
#pragma unroll
    for (int mt = 0; mt < 4; ++mt) {
        int row = mw + mt * 16 + (lane >> 2);
#pragma unroll
        for (int nf = 0; nf < 8; ++nf) {
            int col = nw + nf * 8 + (lane & 3) * 2;
            float b0v = bias[col], b1v = bias[col + 1];
            float2 v0 = make_float2(acc[mt][nf][0] + b0v, acc[mt][nf][1] + b1v);
            float2 v1 = make_float2(acc[mt][nf][2] + b0v, acc[mt][nf][3] + b1v);
            *(float2*)&out[(size_t)row * Ntot + col] = v0;
            *(float2*)&out[(size_t)(row + 8) * Ntot + col] = v1;
        }
    }
}

// ---------------- twiddle init ----------------
__global__ void twiddle_kernel() {
    int j = blockIdx.x * blockDim.x + threadIdx.x;
    if (j < FFT_HN) {
        double s, c;
        sincospi(-2.0 * (double)j / (double)FFT_N, &s, &c);
        g_TW[j] = make_float2((float)c, (float)s);
    }
}

// ---------------- radix-4 FFT (N=8192 = 2 * 4^6, 512 threads) ----------------
__device__ __forceinline__ void fft_fwd4(float2* z) {
#pragma unroll
    for (int r = 0; r < 8; ++r) {
        int t = threadIdx.x + r * FFT_T;
        float2 a = z[t], b = z[t + 4096];
        z[t] = cadd(a, b);
        z[t + 4096] = cmul(csub(a, b), g_TW[t]);
    }
    __syncthreads();
#pragma unroll
    for (int n = 4096; n >= 4; n >>= 2) {
        const int q = n >> 2;
        const int s = FFT_N / n;
#pragma unroll
        for (int r = 0; r < 4; ++r) {
            int t = threadIdx.x + r * FFT_T;
            int j = t & (q - 1);
            int base = ((t / q) * n) + j;
            float2 a0 = z[base], a1 = z[base + q], a2 = z[base + 2 * q], a3 = z[base + 3 * q];
            float2 t0 = cadd(a0, a2), t2 = csub(a0, a2);
            float2 t1 = cadd(a1, a3);
            float2 d13 = csub(a1, a3);
            float2 t3 = make_float2(d13.y, -d13.x);
            float2 w1 = g_TW[j * s], w2 = g_TW[2 * j * s];
            float2 w3 = cmul(w1, w2);
            z[base]         = cadd(t0, t1);
            z[base + q]     = cmul(cadd(t2, t3), w1);
            z[base + 2 * q] = cmul(csub(t0, t1), w2);
            z[base + 3 * q] = cmul(csub(t2, t3), w3);
        }
        __syncthreads();
    }
}
__device__ __forceinline__ void fft_inv4(float2* z) {
#pragma unroll
    for (int n = 4; n <= 4096; n <<= 2) {
        const int q = n >> 2;
        const int s = FFT_N / n;
#pragma unroll
        for (int r = 0; r < 4; ++r) {
            int t = threadIdx.x + r * FFT_T;
            int j = t & (q - 1);
            int base = ((t / q) * n) + j;
            float2 w1 = g_TW[j * s], w2 = g_TW[2 * j * s];
            float2 w3 = cmul(w1, w2);
            float2 c0 = z[base];
            float2 c1 = cmulc(z[base + q], w1);
            float2 c2 = cmulc(z[base + 2 * q], w2);
            float2 c3 = cmulc(z[base + 3 * q], w3);
            float2 s02 = cadd(c0, c2), d02 = csub(c0, c2);
            float2 s13 = cadd(c1, c3), d13 = csub(c1, c3);
            float2 id13 = make_float2(-d13.y, d13.x);
            z[base]         = cadd(s02, s13);
            z[base + q]     = cadd(d02, id13);
            z[base + 2 * q] = csub(s02, s13);
            z[base + 3 * q] = csub(d02, id13);
        }
        __syncthreads();
    }
#pragma unroll
    for (int r = 0; r < 8; ++r) {
        int t = threadIdx.x + r * FFT_T;
        float2 c0 = z[t];
        float2 c1 = cmulc(z[t + 4096], g_TW[t]);
        z[t] = cadd(c0, c1);
        z[t + 4096] = csub(c0, c1);
    }
    __syncthreads();
}

// ---------------- filter MLP ----------------
__global__ void filter_h_kernel(const float* __restrict__ w0, const float* __restrict__ b0,
                                const float* __restrict__ freq,
                                const float* __restrict__ w1, const float* __restrict__ b1,
                                const float* __restrict__ w2, const float* __restrict__ b2,
                                float* __restrict__ H)
{
    const int l = blockIdx.x;
    const int f = threadIdx.x;
    __shared__ float h1s[64];
    __shared__ float h2s[64];
    const float t  = (float)l / (float)(LSEQ - 1);
    const float ang = 1e-4f * 2.0f * 3.14159265358979323846f * (float)l / (float)LSEQ;
    const float z0 = t, z1 = cosf(ang), z2 = -sinf(ang);
    const float fr = freq[f];
    float pre = z0 * w0[f * 3 + 0] + z1 * w0[f * 3 + 1] + z2 * w0[f * 3 + 2] + b0[f];
    h1s[f] = sinf(fr * pre);
    __syncthreads();
    float s = b1[f];
#pragma unroll
    for (int g = 0; g < 64; ++g) s = fmaf(h1s[g], w1[f * 64 + g], s);
    h2s[f] = sinf(fr * s);
    __syncthreads();
    s = b2[f];
#pragma unroll
    for (int g = 0; g < 64; ++g) s = fmaf(h2s[g], w2[f * 64 + g], s);
    H[(size_t)l * 64 + f] = sinf(fr * s);
}

// ---------------- K_time ----------------
__global__ __launch_bounds__(128) void ktime_kernel(const float* __restrict__ H,
                                                    const float* __restrict__ w3,
                                                    float* __restrict__ Kt)
{
    __shared__ float Hs[128][65];
    __shared__ float w3s[16][64];
    const int l0 = blockIdx.x * 128;
    const int d0 = blockIdx.y * 16;
    const int tid = threadIdx.x;
    for (int idx = tid; idx < 128 * 64; idx += 128)
        Hs[idx >> 6][idx & 63] = H[(size_t)(l0 + (idx >> 6)) * 64 + (idx & 63)];
    for (int idx = tid; idx < 16 * 64; idx += 128)
        w3s[idx >> 6][idx & 63] = w3[(size_t)(d0 + (idx >> 6)) * 64 + (idx & 63)];
    __syncthreads();
    const int l = l0 + tid;
    const float t = (float)l / (float)(LSEQ - 1);
    const float MIND = -3.0701134573253943f;
    const float MAXD = -15.350567286626971f;
#pragma unroll 4
    for (int dd = 0; dd < 16; ++dd) {
        int d = d0 + dd;
        float delta = MIND + (MAXD - MIND) * ((float)d / 2047.0f);
        float decay = expf(t * delta);
        float s = 0.f;
#pragma unroll
        for (int f = 0; f < 64; ++f) s = fmaf(Hs[tid][f], w3s[dd][f], s);
        Kt[(size_t)d * LSEQ + l] = s * decay;
    }
}

// ---------------- FFT of filter ----------------
__global__ __launch_bounds__(FFT_T) void fftk_kernel(const float* __restrict__ Kt,
                                                     float2* __restrict__ Kf)
{
    extern __shared__ float2 zf[];
    const int d = blockIdx.x;
    const float* src = &Kt[(size_t)d * LSEQ];
    for (int t = threadIdx.x; t < FFT_N; t += FFT_T)
        zf[t] = make_float2((t < LSEQ) ? src[t] : 0.f, 0.f);
    __syncthreads();
    fft_fwd4(zf);
    float2* dst = &Kf[(size_t)d * FFT_N];
    for (int t = threadIdx.x; t < FFT_N; t += FFT_T) dst[t] = zf[t];
}

// ---------------- fused short-conv + FFT conv + gate ----------------
__global__ __launch_bounds__(FFT_T) void fftconv_fused_kernel(
    const float2* __restrict__ Kf, const float* __restrict__ U,
    const float* __restrict__ sw, const float* __restrict__ sb,
    const float* __restrict__ fbias, float* __restrict__ YG)
{
    extern __shared__ float2 zf[];
    const int d = blockIdx.x;
    const int c1 = d + DMOD, c2 = d + 2 * DMOD;
    const float w00 = sw[d * 3],  w01 = sw[d * 3 + 1],  w02 = sw[d * 3 + 2],  bb0 = sb[d];
    const float w10 = sw[c1 * 3], w11 = sw[c1 * 3 + 1], w12 = sw[c1 * 3 + 2], bb1 = sb[c1];
    const float w20 = sw[c2 * 3], w21 = sw[c2 * 3 + 1], w22 = sw[c2 * 3 + 2], bb2 = sb[c2];

    const float* u1b0 = &U[((size_t)0 * D3 + c1) * LSEQ];
    const float* u2b0 = &U[((size_t)0 * D3 + c2) * LSEQ];
    const float* u1b1 = &U[((size_t)1 * D3 + c1) * LSEQ];
    const float* u2b1 = &U[((size_t)1 * D3 + c2) * LSEQ];

    for (int l = threadIdx.x; l < LSEQ; l += FFT_T) {
        float a2_0 = (l >= 2) ? u1b0[l - 2] : 0.f;
        float a1_0 = (l >= 1) ? u1b0[l - 1] : 0.f;
        float b2_0 = (l >= 2) ? u2b0[l - 2] : 0.f;
        float b1_0 = (l >= 1) ? u2b0[l - 1] : 0.f;
        float x1_0 = fmaf(w10, a2_0, fmaf(w11, a1_0, fmaf(w12, u1b0[l], bb1)));
        float v_0  = fmaf(w20, b2_0, fmaf(w21, b1_0, fmaf(w22, u2b0[l], bb2)));
        float a2_1 = (l >= 2) ? u1b1[l - 2] : 0.f;
        float a1_1 = (l >= 1) ? u1b1[l - 1] : 0.f;
        float b2_1 = (l >= 2) ? u2b1[l - 2] : 0.f;
        float b1_1 = (l >= 1) ? u2b1[l - 1] : 0.f;
        float x1_1 = fmaf(w10, a2_1, fmaf(w11, a1_1, fmaf(w12, u1b1[l], bb1)));
        float v_1  = fmaf(w20, b2_1, fmaf(w21, b1_1, fmaf(w22, u2b1[l], bb2)));
        zf[l] = make_float2(v_0 * x1_0, v_1 * x1_1);
    }
    for (int t = threadIdx.x + LSEQ; t < FFT_N; t += FFT_T)
        zf[t] = make_float2(0.f, 0.f);
    __syncthreads();
    fft_fwd4(zf);
    const float2* kf = &Kf[(size_t)d * FFT_N];
    for (int t = threadIdx.x; t < FFT_N; t += FFT_T)
        zf[t] = cmul(zf[t], kf[t]);
    __syncthreads();
    fft_inv4(zf);

    const float bb = fbias[d];
    const float* u0b0 = &U[((size_t)0 * D3 + d) * LSEQ];
    const float* u0b1 = &U[((size_t)1 * D3 + d) * LSEQ];
    float* y0 = &YG[(size_t)d * LSEQ];
    float* y1 = &YG[((size_t)DMOD + d) * LSEQ];
    const float inv = 1.0f / (float)FFT_N;
    for (int l = threadIdx.x; l < LSEQ; l += FFT_T) {
        float a2_0 = (l >= 2) ? u1b0[l - 2] : 0.f;
        float a1_0 = (l >= 1) ? u1b0[l - 1] : 0.f;
        float b2_0 = (l >= 2) ? u2b0[l - 2] : 0.f;
        float b1_0 = (l >= 1) ? u2b0[l - 1] : 0.f;
        float c2_0 = (l >= 2) ? u0b0[l - 2] : 0.f;
        float c1_0 = (l >= 1) ? u0b0[l - 1] : 0.f;
        float x1_0 = fmaf(w10, a2_0, fmaf(w11, a1_0, fmaf(w12, u1b0[l], bb1)));
        float v_0  = fmaf(w20, b2_0, fmaf(w21, b1_0, fmaf(w22, u2b0[l], bb2)));
        float x0_0 = fmaf(w00, c2_0, fmaf(w01, c1_0, fmaf(w02, u0b0[l], bb0)));
        float a2_1 = (l >= 2) ? u1b1[l - 2] : 0.f;
        float a1_1 = (l >= 1) ? u1b1[l - 1] : 0.f;
        float b2_1 = (l >= 2) ? u2b1[l - 2] : 0.f;
        float b1_1 = (l >= 1) ? u2b1[l - 1] : 0.f;
        float c2_1 = (l >= 2) ? u0b1[l - 2] : 0.f;
        float c1_1 = (l >= 1) ? u0b1[l - 1] : 0.f;
        float x1_1 = fmaf(w10, a2_1, fmaf(w11, a1_1, fmaf(w12, u1b1[l], bb1)));
        float v_1  = fmaf(w20, b2_1, fmaf(w21, b1_1, fmaf(w22, u2b1[l], bb2)));
        float x0_1 = fmaf(w00, c2_1, fmaf(w01, c1_1, fmaf(w02, u0b1[l], bb0)));
        float2 yv = zf[l];
        y0[l] = fmaf(yv.x, inv, bb * (v_0 * x1_0)) * x0_0;
        y1[l] = fmaf(yv.y, inv, bb * (v_1 * x1_1)) * x0_1;
    }
}

// ---------------- launch ----------------
extern "C" void kernel_launch(void* const* d_in, const int* in_sizes, int n_in,
                              void* d_out, int out_size)
{
    const float* x        = (const float*)d_in[0];
    const float* in_w     = (const float*)d_in[1];
    const float* in_b     = (const float*)d_in[2];
    const float* short_w  = (const float*)d_in[3];
    const float* short_b  = (const float*)d_in[4];
    const float* mlp_w0   = (const float*)d_in[5];
    const float* mlp_b0   = (const float*)d_in[6];
    const float* sin_freq = (const float*)d_in[7];
    const float* mlp_w1   = (const float*)d_in[8];
    const float* mlp_b1   = (const float*)d_in[9];
    const float* mlp_w2   = (const float*)d_in[10];
    const float* mlp_b2   = (const float*)d_in[11];
    const float* mlp_w3   = (const float*)d_in[12];
    const float* f_bias   = (const float*)d_in[13];
    const float* out_w    = (const float*)d_in[14];
    const float* out_b    = (const float*)d_in[15];
    float* out = (float*)d_out;

    cudaFuncSetAttribute(fftk_kernel, cudaFuncAttributeMaxDynamicSharedMemorySize, FFT_N * 8);
    cudaFuncSetAttribute(fftconv_fused_kernel, cudaFuncAttributeMaxDynamicSharedMemorySize, FFT_N * 8);
    cudaFuncSetAttribute(mma_gemm_kernel, cudaFuncAttributeMaxDynamicSharedMemorySize, GEMM_SMEM);
    cudaFuncSetAttribute(imma_gemm_kernel<0>, cudaFuncAttributeMaxDynamicSharedMemorySize, QSMEM);
    cudaFuncSetAttribute(imma_gemm_kernel<1>, cudaFuncAttributeMaxDynamicSharedMemorySize, QSMEM);

    float* U;    cudaGetSymbolAddress((void**)&U,    g_U);
    float* H;    cudaGetSymbolAddress((void**)&H,    g_H);
    float* Kt;   cudaGetSymbolAddress((void**)&Kt,   g_Kt);
    float2* Kf;  cudaGetSymbolAddress((void**)&Kf,   g_Kf);
    float* YG;   cudaGetSymbolAddress((void**)&YG,   g_YG);
    int8_t* A1q; cudaGetSymbolAddress((void**)&A1q,  g_A1q);
    int8_t* B1q; cudaGetSymbolAddress((void**)&B1q,  g_B1q);
    float* SA1;  cudaGetSymbolAddress((void**)&SA1,  g_SA1);
    float* SB1;  cudaGetSymbolAddress((void**)&SB1,  g_SB1);
    float* Ctmp; cudaGetSymbolAddress((void**)&Ctmp, g_Ctmp);
    __nv_bfloat16* B2; cudaGetSymbolAddress((void**)&B2, g_B2);
    __nv_bfloat16* A2; cudaGetSymbolAddress((void**)&A2, g_A2);

    // 1-3: quantize / convert operands
    quant_rows_kernel<<<BATCH * LSEQ, 256>>>(x, A1q, SA1);
    quant_rows_kernel<<<D3, 256>>>(in_w, B1q, SB1);
    {
        size_t t4 = (size_t)DMOD * DMOD / 4;
        convert_split_kernel<<<(unsigned)((t4 + 255) / 256), 256>>>(out_w, B2, t4);
    }

    // 4: int8 in_proj cross pass -> Ctmp   [ncu capture slot]
    imma_gemm_kernel<0><<<dim3(D3 / BN, (BATCH * LSEQ) / BM), GEMM_T, QSMEM>>>(
        A1q, B1q, SA1, SB1, in_b, Ctmp, U, D3);
    // 5: int8 in_proj main pass -> U (B,3D,L)
    imma_gemm_kernel<1><<<dim3(D3 / BN, (BATCH * LSEQ) / BM), GEMM_T, QSMEM>>>(
        A1q, B1q, SA1, SB1, in_b, Ctmp, U, D3);

    // 6-9: filter path
    twiddle_kernel<<<16, 256>>>();
    filter_h_kernel<<<LSEQ, 64>>>(mlp_w0, mlp_b0, sin_freq, mlp_w1, mlp_b1, mlp_w2, mlp_b2, H);
    ktime_kernel<<<dim3(LSEQ / 128, DMOD / 16), 128>>>(H, mlp_w3, Kt);
    fftk_kernel<<<DMOD, FFT_T, FFT_N * 8>>>(Kt, Kf);

    // 10: fused short-conv + fftconv + gate
    fftconv_fused_kernel<<<DMOD, FFT_T, FFT_N * 8>>>(Kf, U, short_w, short_b, f_bias, YG);

    // 11: transpose+split YG -> A2 (bf16)
    yg_convert_kernel<<<dim3(LSEQ / 32, DMOD / 32, BATCH), dim3(32, 8)>>>(YG, A2);

    // 12: out_proj GEMM (bf16x3) -> out (B*L, D)
    mma_gemm_kernel<<<dim3(DMOD / BN, (BATCH * LSEQ) / BM), GEMM_T, GEMM_SMEM>>>(
        A2, B2, out_b, out, DMOD);
}

// round 15
// speedup vs baseline: 1.9115x; 1.9115x over previous
#include <cuda_runtime.h>
#include <cuda_bf16.h>
#include <math.h>
#include <stdint.h>

// ---------------- problem constants ----------------
#define BATCH 2
#define LSEQ 4096
#define DMOD 2048
#define D3 6144
#define FORD 64
#define FFT_N 8192
#define FFT_HN 4096
#define FFT_T 512

// bf16x3 split GEMM: logical K = 3*2048, stored packed as [hi | lo] (width 4096)
// segment schedule: A {hi, lo, hi} x B {hi, hi, lo}
#define KPACK 4096
#define KS2 6144
#define BM 128
#define BN 128
#define BK 64
#define NCHUNK (KS2 / BK)          // 96
#define STAGE 32768                // A 16KB + B 16KB
#define NSTAGE 3
#define GEMM_SMEM (NSTAGE * STAGE) // 96KB -> 2 CTAs/SM
#define GEMM_T 128                 // 4 warps, 2x2 grid of 64x64 warp tiles
#define SUPER_M 16

// ---------------- device scratch ----------------
__device__ float  g_U[(size_t)BATCH * D3 * LSEQ];
__device__ float  g_H[(size_t)LSEQ * FORD];
__device__ float  g_Kt[(size_t)DMOD * LSEQ];
__device__ float2 g_Kf[(size_t)DMOD * FFT_N];
__device__ float  g_YG[(size_t)BATCH * DMOD * LSEQ];
__device__ float2 g_TW[FFT_HN];
__device__ __nv_bfloat16 g_A1[(size_t)BATCH * LSEQ * KPACK];
__device__ __nv_bfloat16 g_B1[(size_t)D3 * KPACK];
__device__ __nv_bfloat16 g_B2[(size_t)DMOD * KPACK];
__device__ __nv_bfloat16 g_A2[(size_t)BATCH * LSEQ * KPACK];

// ---------------- PTX helpers (baseline ISA only) ----------------
__device__ __forceinline__ uint32_t smem_to_u32(const void* p) {
    uint32_t a;
    asm("{ .reg .u64 t; cvta.to.shared.u64 t, %1; cvt.u32.u64 %0, t; }" : "=r"(a) : "l"(p));
    return a;
}
#define SWZ(o) ((o) ^ (((o) >> 3) & 0x70))

#define CP_ASYNC16(dst, src) \
    asm volatile("cp.async.cg.shared.global [%0], [%1], 16;" :: "r"(dst), "l"(src))
#define CP_COMMIT() asm volatile("cp.async.commit_group;" ::: "memory")
#define CP_WAIT1()  asm volatile("cp.async.wait_group 1;" ::: "memory")

#define LDSM_X4(r0, r1, r2, r3, addr)                                         \
    asm volatile("ldmatrix.sync.aligned.m8n8.x4.shared.b16 {%0,%1,%2,%3}, [%4];" \
                 : "=r"(r0), "=r"(r1), "=r"(r2), "=r"(r3) : "r"(addr))

#define MMA16816(c, a, b)                                                     \
    asm volatile("mma.sync.aligned.m16n8k16.row.col.f32.bf16.bf16.f32 "       \
                 "{%0,%1,%2,%3}, {%4,%5,%6,%7}, {%8,%9}, {%0,%1,%2,%3};"      \
                 : "+f"((c)[0]), "+f"((c)[1]), "+f"((c)[2]), "+f"((c)[3])     \
                 : "r"((a)[0]), "r"((a)[1]), "r"((a)[2]), "r"((a)[3]),        \
                   "r"((b)[0]), "r"((b)[1]))

// ---------------- complex helpers ----------------
__device__ __forceinline__ float2 cadd(float2 a, float2 b) { return make_float2(a.x + b.x, a.y + b.y); }
__device__ __forceinline__ float2 csub(float2 a, float2 b) { return make_float2(a.x - b.x, a.y - b.y); }
__device__ __forceinline__ float2 cmul(float2 a, float2 b) {
    return make_float2(a.x * b.x - a.y * b.y, a.x * b.y + a.y * b.x);
}
__device__ __forceinline__ float2 cmulc(float2 a, float2 b) {
    return make_float2(a.x * b.x + a.y * b.y, a.y * b.x - a.x * b.y);
}

// ---------------- split converter: fp32 (rows,2048) -> bf16 [hi | lo] ----------------
__global__ void convert_split_kernel(const float* __restrict__ src,
                                     __nv_bfloat16* __restrict__ dst, size_t total4)
{
    size_t i = (size_t)blockIdx.x * blockDim.x + threadIdx.x;
    if (i >= total4) return;
    float4 v = ((const float4*)src)[i];
    size_t e = i * 4;
    size_t r = e >> 11;
    int k = (int)(e & 2047);
    float f[4] = {v.x, v.y, v.z, v.w};
    __nv_bfloat16 h[4], l[4];
#pragma unroll
    for (int j = 0; j < 4; ++j) {
        h[j] = __float2bfloat16(f[j]);
        l[j] = __float2bfloat16(f[j] - __bfloat162float(h[j]));
    }
    __nv_bfloat16* base = dst + r * KPACK + k;
    *(__nv_bfloat162*)(base)            = __nv_bfloat162(h[0], h[1]);
    *(__nv_bfloat162*)(base + 2)        = __nv_bfloat162(h[2], h[3]);
    *(__nv_bfloat162*)(base + 2048)     = __nv_bfloat162(l[0], l[1]);
    *(__nv_bfloat162*)(base + 2048 + 2) = __nv_bfloat162(l[2], l[3]);
}

// YG (B,D,L) -> A2 (b*L+l, [hi|lo]) via 32x32 smem transpose
__global__ void yg_convert_kernel(const float* __restrict__ YG, __nv_bfloat16* __restrict__ A2)
{
    __shared__ float tile[32][33];
    const int b = blockIdx.z;
    const int d0 = blockIdx.y * 32;
    const int l0 = blockIdx.x * 32;
    const int tx = threadIdx.x, ty = threadIdx.y;
    for (int i = ty; i < 32; i += 8)
        tile[i][tx] = YG[((size_t)b * DMOD + d0 + i) * LSEQ + l0 + tx];
    __syncthreads();
    for (int i = ty; i < 32; i += 8) {
        float v = tile[tx][i];
        __nv_bfloat16 h = __float2bfloat16(v);
        __nv_bfloat16 l = __float2bfloat16(v - __bfloat162float(h));
        size_t m = (size_t)b * LSEQ + l0 + i;
        A2[m * KPACK + d0 + tx]        = h;
        A2[m * KPACK + 2048 + d0 + tx] = l;
    }
}

// ---------------- mma.sync GEMM: 128 threads, 2x2 warps of 64x64 ----------------
__device__ __forceinline__ void load_stage(uint32_t sA, uint32_t sB,
                                           const __nv_bfloat16* __restrict__ A,
                                           const __nv_bfloat16* __restrict__ Bm,
                                           int m0, int n0, int kA, int kB, int tid)
{
#pragma unroll
    for (int i = 0; i < 8; ++i) {
        int g = tid + i * GEMM_T;
        int row = g >> 3, seg = g & 7;
        const void* gp = A + (size_t)(m0 + row) * KPACK + kA + seg * 8;
        uint32_t off = (uint32_t)(row * 128 + seg * 16);
        CP_ASYNC16(sA + SWZ(off), gp);
    }
#pragma unroll
    for (int i = 0; i < 8; ++i) {
        int g = tid + i * GEMM_T;
        int row = g >> 3, seg = g & 7;
        const void* gp = Bm + (size_t)(n0 + row) * KPACK + kB + seg * 8;
        uint32_t off = (uint32_t)(row * 128 + seg * 16);
        CP_ASYNC16(sB + SWZ(off), gp);
    }
}

__device__ __forceinline__ void compute_chunk(uint32_t sA, uint32_t sB,
                                              int lane, int wm, int wn,
                                              float acc[4][8][4])
{
    const int rlow = lane & 15;
    const int khalf = (lane >> 4) * 16;
#pragma unroll
    for (int kk = 0; kk < 4; ++kk) {
        const int kb = kk * 32 + khalf;
        uint32_t af[4][4], bf[8][2];
#pragma unroll
        for (int mt = 0; mt < 4; ++mt) {
            uint32_t off = (uint32_t)((wm * 64 + mt * 16 + rlow) * 128 + kb);
            LDSM_X4(af[mt][0], af[mt][1], af[mt][2], af[mt][3], sA + SWZ(off));
        }
#pragma unroll
        for (int nb = 0; nb < 4; ++nb) {
            uint32_t r0, r1, r2, r3;
            uint32_t off = (uint32_t)((wn * 64 + nb * 16 + rlow) * 128 + kb);
            LDSM_X4(r0, r1, r2, r3, sB + SWZ(off));
            bf[nb * 2][0] = r0; bf[nb * 2][1] = r2;
            bf[nb * 2 + 1][0] = r1; bf[nb * 2 + 1][1] = r3;
        }
#pragma unroll
        for (int mt = 0; mt < 4; ++mt)
#pragma unroll
            for (int nf = 0; nf < 8; ++nf)
                MMA16816(acc[mt][nf], af[mt], bf[nf]);
    }
}

// segment column maps: A {hi,lo,hi}, B {hi,hi,lo} over packed [hi|lo]
__device__ __forceinline__ int mapA(int k0) { int s = k0 >> 11; return ((s & 1) << 11) + (k0 & 2047); }
__device__ __forceinline__ int mapB(int k0) { int s = k0 >> 11; return ((s >> 1) << 11) + (k0 & 2047); }

// MODE 0: row-major out (ld = Ntot).  MODE 1: transposed store into U (B,3D,L).
template <int MODE>
__global__ __launch_bounds__(GEMM_T, 2) void mma_gemm_kernel(
    const __nv_bfloat16* __restrict__ A, const __nv_bfloat16* __restrict__ Bm,
    const float* __restrict__ bias, float* __restrict__ out, int Ntot)
{
    extern __shared__ char smem[];
    const uint32_t sbase = smem_to_u32(smem);
    const int tid = threadIdx.x;
    const int lane = tid & 31, wid = tid >> 5;
    const int wm = wid >> 1, wn = wid & 1;

    int bid = blockIdx.y * gridDim.x + blockIdx.x;
    int per = SUPER_M * gridDim.x;
    int sup = bid / per, rem = bid % per;
    const int m0 = (sup * SUPER_M + (rem & (SUPER_M - 1))) * BM;
    const int n0 = (rem / SUPER_M) * BN;

    float acc[4][8][4];
#pragma unroll
    for (int a = 0; a < 4; ++a)
#pragma unroll
        for (int b = 0; b < 8; ++b)
#pragma unroll
            for (int c = 0; c < 4; ++c) acc[a][b][c] = 0.f;

    load_stage(sbase, sbase + 16384, A, Bm, m0, n0, mapA(0), mapB(0), tid);
    CP_COMMIT();
    load_stage(sbase + STAGE, sbase + STAGE + 16384, A, Bm, m0, n0, mapA(BK), mapB(BK), tid);
    CP_COMMIT();

    for (int c = 0; c < NCHUNK; ++c) {
        CP_WAIT1();
        __syncthreads();
        if (c + 2 < NCHUNK) {
            int st = (c + 2) % NSTAGE;
            int k0 = (c + 2) * BK;
            load_stage(sbase + st * STAGE, sbase + st * STAGE + 16384,
                       A, Bm, m0, n0, mapA(k0), mapB(k0), tid);
        }
        CP_COMMIT();
        int st = c % NSTAGE;
        compute_chunk(sbase + st * STAGE, sbase + st * STAGE + 16384, lane, wm, wn, acc);
    }
    __syncthreads();

    if (MODE == 0) {
        const int mw = m0 + wm * 64, nw = n0 + wn * 64;
#pragma unroll
        for (int mt = 0; mt < 4; ++mt) {
            int row = mw + mt * 16 + (lane >> 2);
#pragma unroll
            for (int nf = 0; nf < 8; ++nf) {
                int col = nw + nf * 8 + (lane & 3) * 2;
                float b0v = bias[col], b1v = bias[col + 1];
                float2 v0 = make_float2(acc[mt][nf][0] + b0v, acc[mt][nf][1] + b1v);
                float2 v1 = make_float2(acc[mt][nf][2] + b0v, acc[mt][nf][3] + b1v);
                *(float2*)&out[(size_t)row * Ntot + col] = v0;
                *(float2*)&out[(size_t)(row + 8) * Ntot + col] = v1;
            }
        }
    } else {
        float (*sc)[132] = (float(*)[132])smem;   // 128 x 132 fp32 = 67.6KB <= 96KB
#pragma unroll
        for (int mt = 0; mt < 4; ++mt) {
            int ml = wm * 64 + mt * 16 + (lane >> 2);
#pragma unroll
            for (int nf = 0; nf < 8; ++nf) {
                int nl = wn * 64 + nf * 8 + (lane & 3) * 2;
                sc[nl][ml]         = acc[mt][nf][0];
                sc[nl + 1][ml]     = acc[mt][nf][1];
                sc[nl][ml + 8]     = acc[mt][nf][2];
                sc[nl + 1][ml + 8] = acc[mt][nf][3];
            }
        }
        __syncthreads();
        const int b = m0 >> 12;
        const int lbase = m0 & (LSEQ - 1);
        const int n = tid;
        const float bb = bias[n0 + n];
        float* dst = out + ((size_t)b * D3 + n0 + n) * LSEQ + lbase;
        const float* srow = &sc[n][0];
#pragma unroll
        for (int i = 0; i < 32; ++i) {
            float4 v = *(const float4*)(srow + i * 4);
            v.x += bb; v.y += bb; v.z += bb; v.w += bb;
            *(float4*)(dst + i * 4) = v;
        }
    }
}

// ---------------- twiddle init ----------------
__global__ void twiddle_kernel() {
    int j = blockIdx.x * blockDim.x + threadIdx.x;
    if (j < FFT_HN) {
        double s, c;
        sincospi(-2.0 * (double)j / (double)FFT_N, &s, &c);
        g_TW[j] = make_float2((float)c, (float)s);
    }
}

// ---------------- radix-4 FFT (N=8192 = 2 * 4^6, 512 threads) ----------------
__device__ __forceinline__ void fft_fwd4(float2* z) {
#pragma unroll
    for (int r = 0; r < 8; ++r) {
        int t = threadIdx.x + r * FFT_T;
        float2 a = z[t], b = z[t + 4096];
        z[t] = cadd(a, b);
        z[t + 4096] = cmul(csub(a, b), g_TW[t]);
    }
    __syncthreads();
#pragma unroll
    for (int n = 4096; n >= 4; n >>= 2) {
        const int q = n >> 2;
        const int s = FFT_N / n;
#pragma unroll
        for (int r = 0; r < 4; ++r) {
            int t = threadIdx.x + r * FFT_T;
            int j = t & (q - 1);
            int base = ((t / q) * n) + j;
            float2 a0 = z[base], a1 = z[base + q], a2 = z[base + 2 * q], a3 = z[base + 3 * q];
            float2 t0 = cadd(a0, a2), t2 = csub(a0, a2);
            float2 t1 = cadd(a1, a3);
            float2 d13 = csub(a1, a3);
            float2 t3 = make_float2(d13.y, -d13.x);
            float2 w1 = g_TW[j * s], w2 = g_TW[2 * j * s];
            float2 w3 = cmul(w1, w2);
            z[base]         = cadd(t0, t1);
            z[base + q]     = cmul(cadd(t2, t3), w1);
            z[base + 2 * q] = cmul(csub(t0, t1), w2);
            z[base + 3 * q] = cmul(csub(t2, t3), w3);
        }
        __syncthreads();
    }
}
__device__ __forceinline__ void fft_inv4(float2* z) {
#pragma unroll
    for (int n = 4; n <= 4096; n <<= 2) {
        const int q = n >> 2;
        const int s = FFT_N / n;
#pragma unroll
        for (int r = 0; r < 4; ++r) {
            int t = threadIdx.x + r * FFT_T;
            int j = t & (q - 1);
            int base = ((t / q) * n) + j;
            float2 w1 = g_TW[j * s], w2 = g_TW[2 * j * s];
            float2 w3 = cmul(w1, w2);
            float2 c0 = z[base];
            float2 c1 = cmulc(z[base + q], w1);
            float2 c2 = cmulc(z[base + 2 * q], w2);
            float2 c3 = cmulc(z[base + 3 * q], w3);
            float2 s02 = cadd(c0, c2), d02 = csub(c0, c2);
            float2 s13 = cadd(c1, c3), d13 = csub(c1, c3);
            float2 id13 = make_float2(-d13.y, d13.x);
            z[base]         = cadd(s02, s13);
            z[base + q]     = cadd(d02, id13);
            z[base + 2 * q] = csub(s02, s13);
            z[base + 3 * q] = csub(d02, id13);
        }
        __syncthreads();
    }
#pragma unroll
    for (int r = 0; r < 8; ++r) {
        int t = threadIdx.x + r * FFT_T;
        float2 c0 = z[t];
        float2 c1 = cmulc(z[t + 4096], g_TW[t]);
        z[t] = cadd(c0, c1);
        z[t + 4096] = csub(c0, c1);
    }
    __syncthreads();
}

// ---------------- filter MLP ----------------
__global__ void filter_h_kernel(const float* __restrict__ w0, const float* __restrict__ b0,
                                const float* __restrict__ freq,
                                const float* __restrict__ w1, const float* __restrict__ b1,
                                const float* __restrict__ w2, const float* __restrict__ b2,
                                float* __restrict__ H)
{
    const int l = blockIdx.x;
    const int f = threadIdx.x;
    __shared__ float h1s[64];
    __shared__ float h2s[64];
    const float t  = (float)l / (float)(LSEQ - 1);
    const float ang = 1e-4f * 2.0f * 3.14159265358979323846f * (float)l / (float)LSEQ;
    const float z0 = t, z1 = cosf(ang), z2 = -sinf(ang);
    const float fr = freq[f];
    float pre = z0 * w0[f * 3 + 0] + z1 * w0[f * 3 + 1] + z2 * w0[f * 3 + 2] + b0[f];
    h1s[f] = sinf(fr * pre);
    __syncthreads();
    float s = b1[f];
#pragma unroll
    for (int g = 0; g < 64; ++g) s = fmaf(h1s[g], w1[f * 64 + g], s);
    h2s[f] = sinf(fr * s);
    __syncthreads();
    s = b2[f];
#pragma unroll
    for (int g = 0; g < 64; ++g) s = fmaf(h2s[g], w2[f * 64 + g], s);
    H[(size_t)l * 64 + f] = sinf(fr * s);
}

// ---------------- K_time ----------------
__global__ __launch_bounds__(128) void ktime_kernel(const float* __restrict__ H,
                                                    const float* __restrict__ w3,
                                                    float* __restrict__ Kt)
{
    __shared__ float Hs[128][65];
    __shared__ float w3s[16][64];
    const int l0 = blockIdx.x * 128;
    const int d0 = blockIdx.y * 16;
    const int tid = threadIdx.x;
    for (int idx = tid; idx < 128 * 64; idx += 128)
        Hs[idx >> 6][idx & 63] = H[(size_t)(l0 + (idx >> 6)) * 64 + (idx & 63)];
    for (int idx = tid; idx < 16 * 64; idx += 128)
        w3s[idx >> 6][idx & 63] = w3[(size_t)(d0 + (idx >> 6)) * 64 + (idx & 63)];
    __syncthreads();
    const int l = l0 + tid;
    const float t = (float)l / (float)(LSEQ - 1);
    const float MIND = -3.0701134573253943f;
    const float MAXD = -15.350567286626971f;
#pragma unroll 4
    for (int dd = 0; dd < 16; ++dd) {
        int d = d0 + dd;
        float delta = MIND + (MAXD - MIND) * ((float)d / 2047.0f);
        float decay = expf(t * delta);
        float s = 0.f;
#pragma unroll
        for (int f = 0; f < 64; ++f) s = fmaf(Hs[tid][f], w3s[dd][f], s);
        Kt[(size_t)d * LSEQ + l] = s * decay;
    }
}

// ---------------- FFT of filter ----------------
__global__ __launch_bounds__(FFT_T) void fftk_kernel(const float* __restrict__ Kt,
                                                     float2* __restrict__ Kf)
{
    extern __shared__ float2 zf[];
    const int d = blockIdx.x;
    const float* src = &Kt[(size_t)d * LSEQ];
    for (int t = threadIdx.x; t < FFT_N; t += FFT_T)
        zf[t] = make_float2((t < LSEQ) ? src[t] : 0.f, 0.f);
    __syncthreads();
    fft_fwd4(zf);
    float2* dst = &Kf[(size_t)d * FFT_N];
    for (int t = threadIdx.x; t < FFT_N; t += FFT_T) dst[t] = zf[t];
}

// ---------------- fused short-conv + FFT conv + gate ----------------
__global__ __launch_bounds__(FFT_T) void fftconv_fused_kernel(
    const float2* __restrict__ Kf, const float* __restrict__ U,
    const float* __restrict__ sw, const float* __restrict__ sb,
    const float* __restrict__ fbias, float* __restrict__ YG)
{
    extern __shared__ float2 zf[];
    const int d = blockIdx.x;
    const int c1 = d + DMOD, c2 = d + 2 * DMOD;
    const float w00 = sw[d * 3],  w01 = sw[d * 3 + 1],  w02 = sw[d * 3 + 2],  bb0 = sb[d];
    const float w10 = sw[c1 * 3], w11 = sw[c1 * 3 + 1], w12 = sw[c1 * 3 + 2], bb1 = sb[c1];
    const float w20 = sw[c2 * 3], w21 = sw[c2 * 3 + 1], w22 = sw[c2 * 3 + 2], bb2 = sb[c2];

    const float* u1b0 = &U[((size_t)0 * D3 + c1) * LSEQ];
    const float* u2b0 = &U[((size_t)0 * D3 + c2) * LSEQ];
    const float* u1b1 = &U[((size_t)1 * D3 + c1) * LSEQ];
    const float* u2b1 = &U[((size_t)1 * D3 + c2) * LSEQ];

    for (int l = threadIdx.x; l < LSEQ; l += FFT_T) {
        float a2_0 = (l >= 2) ? u1b0[l - 2] : 0.f;
        float a1_0 = (l >= 1) ? u1b0[l - 1] : 0.f;
        float b2_0 = (l >= 2) ? u2b0[l - 2] : 0.f;
        float b1_0 = (l >= 1) ? u2b0[l - 1] : 0.f;
        float x1_0 = fmaf(w10, a2_0, fmaf(w11, a1_0, fmaf(w12, u1b0[l], bb1)));
        float v_0  = fmaf(w20, b2_0, fmaf(w21, b1_0, fmaf(w22, u2b0[l], bb2)));
        float a2_1 = (l >= 2) ? u1b1[l - 2] : 0.f;
        float a1_1 = (l >= 1) ? u1b1[l - 1] : 0.f;
        float b2_1 = (l >= 2) ? u2b1[l - 2] : 0.f;
        float b1_1 = (l >= 1) ? u2b1[l - 1] : 0.f;
        float x1_1 = fmaf(w10, a2_1, fmaf(w11, a1_1, fmaf(w12, u1b1[l], bb1)));
        float v_1  = fmaf(w20, b2_1, fmaf(w21, b1_1, fmaf(w22, u2b1[l], bb2)));
        zf[l] = make_float2(v_0 * x1_0, v_1 * x1_1);
    }
    for (int t = threadIdx.x + LSEQ; t < FFT_N; t += FFT_T)
        zf[t] = make_float2(0.f, 0.f);
    __syncthreads();
    fft_fwd4(zf);
    const float2* kf = &Kf[(size_t)d * FFT_N];
    for (int t = threadIdx.x; t < FFT_N; t += FFT_T)
        zf[t] = cmul(zf[t], kf[t]);
    __syncthreads();
    fft_inv4(zf);

    const float bb = fbias[d];
    const float* u0b0 = &U[((size_t)0 * D3 + d) * LSEQ];
    const float* u0b1 = &U[((size_t)1 * D3 + d) * LSEQ];
    float* y0 = &YG[(size_t)d * LSEQ];
    float* y1 = &YG[((size_t)DMOD + d) * LSEQ];
    const float inv = 1.0f / (float)FFT_N;
    for (int l = threadIdx.x; l < LSEQ; l += FFT_T) {
        float a2_0 = (l >= 2) ? u1b0[l - 2] : 0.f;
        float a1_0 = (l >= 1) ? u1b0[l - 1] : 0.f;
        float b2_0 = (l >= 2) ? u2b0[l - 2] : 0.f;
        float b1_0 = (l >= 1) ? u2b0[l - 1] : 0.f;
        float c2_0 = (l >= 2) ? u0b0[l - 2] : 0.f;
        float c1_0 = (l >= 1) ? u0b0[l - 1] : 0.f;
        float x1_0 = fmaf(w10, a2_0, fmaf(w11, a1_0, fmaf(w12, u1b0[l], bb1)));
        float v_0  = fmaf(w20, b2_0, fmaf(w21, b1_0, fmaf(w22, u2b0[l], bb2)));
        float x0_0 = fmaf(w00, c2_0, fmaf(w01, c1_0, fmaf(w02, u0b0[l], bb0)));
        float a2_1 = (l >= 2) ? u1b1[l - 2] : 0.f;
        float a1_1 = (l >= 1) ? u1b1[l - 1] : 0.f;
        float b2_1 = (l >= 2) ? u2b1[l - 2] : 0.f;
        float b1_1 = (l >= 1) ? u2b1[l - 1] : 0.f;
        float c2_1 = (l >= 2) ? u0b1[l - 2] : 0.f;
        float c1_1 = (l >= 1) ? u0b1[l - 1] : 0.f;
        float x1_1 = fmaf(w10, a2_1, fmaf(w11, a1_1, fmaf(w12, u1b1[l], bb1)));
        float v_1  = fmaf(w20, b2_1, fmaf(w21, b1_1, fmaf(w22, u2b1[l], bb2)));
        float x0_1 = fmaf(w00, c2_1, fmaf(w01, c1_1, fmaf(w02, u0b1[l], bb0)));
        float2 yv = zf[l];
        y0[l] = fmaf(yv.x, inv, bb * (v_0 * x1_0)) * x0_0;
        y1[l] = fmaf(yv.y, inv, bb * (v_1 * x1_1)) * x0_1;
    }
}

// ---------------- launch ----------------
extern "C" void kernel_launch(void* const* d_in, const int* in_sizes, int n_in,
                              void* d_out, int out_size)
{
    const float* x        = (const float*)d_in[0];
    const float* in_w     = (const float*)d_in[1];
    const float* in_b     = (const float*)d_in[2];
    const float* short_w  = (const float*)d_in[3];
    const float* short_b  = (const float*)d_in[4];
    const float* mlp_w0   = (const float*)d_in[5];
    const float* mlp_b0   = (const float*)d_in[6];
    const float* sin_freq = (const float*)d_in[7];
    const float* mlp_w1   = (const float*)d_in[8];
    const float* mlp_b1   = (const float*)d_in[9];
    const float* mlp_w2   = (const float*)d_in[10];
    const float* mlp_b2   = (const float*)d_in[11];
    const float* mlp_w3   = (const float*)d_in[12];
    const float* f_bias   = (const float*)d_in[13];
    const float* out_w    = (const float*)d_in[14];
    const float* out_b    = (const float*)d_in[15];
    float* out = (float*)d_out;

    cudaFuncSetAttribute(fftk_kernel, cudaFuncAttributeMaxDynamicSharedMemorySize, FFT_N * 8);
    cudaFuncSetAttribute(fftconv_fused_kernel, cudaFuncAttributeMaxDynamicSharedMemorySize, FFT_N * 8);
    cudaFuncSetAttribute(mma_gemm_kernel<0>, cudaFuncAttributeMaxDynamicSharedMemorySize, GEMM_SMEM);
    cudaFuncSetAttribute(mma_gemm_kernel<1>, cudaFuncAttributeMaxDynamicSharedMemorySize, GEMM_SMEM);

    float* U;   cudaGetSymbolAddress((void**)&U,   g_U);
    float* H;   cudaGetSymbolAddress((void**)&H,   g_H);
    float* Kt;  cudaGetSymbolAddress((void**)&Kt,  g_Kt);
    float2* Kf; cudaGetSymbolAddress((void**)&Kf,  g_Kf);
    float* YG;  cudaGetSymbolAddress((void**)&YG,  g_YG);
    __nv_bfloat16* A1; cudaGetSymbolAddress((void**)&A1, g_A1);
    __nv_bfloat16* B1; cudaGetSymbolAddress((void**)&B1, g_B1);
    __nv_bfloat16* B2; cudaGetSymbolAddress((void**)&B2, g_B2);
    __nv_bfloat16* A2; cudaGetSymbolAddress((void**)&A2, g_A2);

    // Side stream + events, created ONCE during the (uncaptured) correctness
    // call; reused as capture-legal fork/join nodes during graph capture.
    static cudaStream_t s_side = nullptr;
    static cudaEvent_t s_fork = nullptr, s_join = nullptr;
    if (s_side == nullptr) {
        cudaStreamCreateWithFlags(&s_side, cudaStreamNonBlocking);
        cudaEventCreateWithFlags(&s_fork, cudaEventDisableTiming);
        cudaEventCreateWithFlags(&s_join, cudaEventDisableTiming);
    }

    // ---- fork: filter path + B2 convert run on side stream under gemm1 ----
    cudaEventRecord(s_fork, 0);
    cudaStreamWaitEvent(s_side, s_fork, 0);

    // main stream: operand converts for gemm1, then gemm1
    {
        size_t t4 = (size_t)BATCH * LSEQ * DMOD / 4;
        convert_split_kernel<<<(unsigned)((t4 + 255) / 256), 256>>>(x, A1, t4);
        t4 = (size_t)D3 * DMOD / 4;
        convert_split_kernel<<<(unsigned)((t4 + 255) / 256), 256>>>(in_w, B1, t4);
    }
    mma_gemm_kernel<1><<<dim3(D3 / BN, (BATCH * LSEQ) / BM), GEMM_T, GEMM_SMEM>>>(
        A1, B1, in_b, U, D3);

    // side stream: filter path + out_proj weight convert
    twiddle_kernel<<<16, 256, 0, s_side>>>();
    filter_h_kernel<<<LSEQ, 64, 0, s_side>>>(mlp_w0, mlp_b0, sin_freq,
                                             mlp_w1, mlp_b1, mlp_w2, mlp_b2, H);
    ktime_kernel<<<dim3(LSEQ / 128, DMOD / 16), 128, 0, s_side>>>(H, mlp_w3, Kt);
    fftk_kernel<<<DMOD, FFT_T, FFT_N * 8, s_side>>>(Kt, Kf);
    {
        size_t t4 = (size_t)DMOD * DMOD / 4;
        convert_split_kernel<<<(unsigned)((t4 + 255) / 256), 256, 0, s_side>>>(out_w, B2, t4);
    }

    // ---- join: main stream waits for filter path before fftconv ----
    cudaEventRecord(s_join, s_side);
    cudaStreamWaitEvent(0, s_join, 0);

    // fused short-conv + fftconv + gate (needs U, Kf, g_TW)
    fftconv_fused_kernel<<<DMOD, FFT_T, FFT_N * 8>>>(Kf, U, short_w, short_b, f_bias, YG);

    // transpose+split YG -> A2
    yg_convert_kernel<<<dim3(LSEQ / 32, DMOD / 32, BATCH), dim3(32, 8)>>>(YG, A2);

    // out_proj GEMM -> out (B*L, D)
    mma_gemm_kernel<0><<<dim3(DMOD / BN, (BATCH * LSEQ) / BM), GEMM_T, GEMM_SMEM>>>(
        A2, B2, out_b, out, DMOD);
}

// round 16
// speedup vs baseline: 1.9251x; 1.0071x over previous
#include <cuda_runtime.h>
#include <cuda_bf16.h>
#include <math.h>
#include <stdint.h>

// ---------------- problem constants ----------------
#define BATCH 2
#define LSEQ 4096
#define DMOD 2048
#define D3 6144
#define FORD 64
#define FFT_N 8192
#define FFT_HN 4096
#define FFT_T 512

// bf16x3 split GEMM: packed [hi | lo] (width 4096); schedule A{hi,lo,hi} x B{hi,hi,lo}
#define KPACK 4096
#define KS2 6144
#define BM 128
#define BN 128
#define BK 64
#define NCHUNK (KS2 / BK)          // 96 (gemm1)
#define NCHUNK2 48                 // gemm2 per-half: 3*1024/64
#define STAGE 32768                // A 16KB + B 16KB
#define NSTAGE 3
#define GEMM_SMEM (NSTAGE * STAGE) // 96KB -> 2 CTAs/SM
#define GEMM_T 128                 // 4 warps, 2x2 grid of 64x64 warp tiles
#define SUPER_M 16
#define DHALF 1024

// ---------------- device scratch ----------------
__device__ float  g_U[(size_t)BATCH * D3 * LSEQ];
__device__ float  g_H[(size_t)LSEQ * FORD];
__device__ float  g_Kt[(size_t)DMOD * LSEQ];
__device__ float2 g_Kf[(size_t)DMOD * FFT_N];
__device__ float  g_YG[(size_t)BATCH * DMOD * LSEQ];
__device__ float2 g_TW[FFT_HN];
__device__ __nv_bfloat16 g_A1[(size_t)BATCH * LSEQ * KPACK];
__device__ __nv_bfloat16 g_B1[(size_t)D3 * KPACK];
__device__ __nv_bfloat16 g_B2[(size_t)DMOD * KPACK];
__device__ __nv_bfloat16 g_A2[(size_t)BATCH * LSEQ * KPACK];

// ---------------- PTX helpers (baseline ISA only) ----------------
__device__ __forceinline__ uint32_t smem_to_u32(const void* p) {
    uint32_t a;
    asm("{ .reg .u64 t; cvta.to.shared.u64 t, %1; cvt.u32.u64 %0, t; }" : "=r"(a) : "l"(p));
    return a;
}
#define SWZ(o) ((o) ^ (((o) >> 3) & 0x70))

#define CP_ASYNC16(dst, src) \
    asm volatile("cp.async.cg.shared.global [%0], [%1], 16;" :: "r"(dst), "l"(src))
#define CP_COMMIT() asm volatile("cp.async.commit_group;" ::: "memory")
#define CP_WAIT1()  asm volatile("cp.async.wait_group 1;" ::: "memory")

#define LDSM_X4(r0, r1, r2, r3, addr)                                         \
    asm volatile("ldmatrix.sync.aligned.m8n8.x4.shared.b16 {%0,%1,%2,%3}, [%4];" \
                 : "=r"(r0), "=r"(r1), "=r"(r2), "=r"(r3) : "r"(addr))

#define MMA16816(c, a, b)                                                     \
    asm volatile("mma.sync.aligned.m16n8k16.row.col.f32.bf16.bf16.f32 "       \
                 "{%0,%1,%2,%3}, {%4,%5,%6,%7}, {%8,%9}, {%0,%1,%2,%3};"      \
                 : "+f"((c)[0]), "+f"((c)[1]), "+f"((c)[2]), "+f"((c)[3])     \
                 : "r"((a)[0]), "r"((a)[1]), "r"((a)[2]), "r"((a)[3]),        \
                   "r"((b)[0]), "r"((b)[1]))

// ---------------- complex helpers ----------------
__device__ __forceinline__ float2 cadd(float2 a, float2 b) { return make_float2(a.x + b.x, a.y + b.y); }
__device__ __forceinline__ float2 csub(float2 a, float2 b) { return make_float2(a.x - b.x, a.y - b.y); }
__device__ __forceinline__ float2 cmul(float2 a, float2 b) {
    return make_float2(a.x * b.x - a.y * b.y, a.x * b.y + a.y * b.x);
}
__device__ __forceinline__ float2 cmulc(float2 a, float2 b) {
    return make_float2(a.x * b.x + a.y * b.y, a.y * b.x - a.x * b.y);
}

// ---------------- split converter: fp32 (rows,2048) -> bf16 [hi | lo] ----------------
__global__ void convert_split_kernel(const float* __restrict__ src,
                                     __nv_bfloat16* __restrict__ dst, size_t total4)
{
    size_t i = (size_t)blockIdx.x * blockDim.x + threadIdx.x;
    if (i >= total4) return;
    float4 v = ((const float4*)src)[i];
    size_t e = i * 4;
    size_t r = e >> 11;
    int k = (int)(e & 2047);
    float f[4] = {v.x, v.y, v.z, v.w};
    __nv_bfloat16 h[4], l[4];
#pragma unroll
    for (int j = 0; j < 4; ++j) {
        h[j] = __float2bfloat16(f[j]);
        l[j] = __float2bfloat16(f[j] - __bfloat162float(h[j]));
    }
    __nv_bfloat16* base = dst + r * KPACK + k;
    *(__nv_bfloat162*)(base)            = __nv_bfloat162(h[0], h[1]);
    *(__nv_bfloat162*)(base + 2)        = __nv_bfloat162(h[2], h[3]);
    *(__nv_bfloat162*)(base + 2048)     = __nv_bfloat162(l[0], l[1]);
    *(__nv_bfloat162*)(base + 2048 + 2) = __nv_bfloat162(l[2], l[3]);
}

// YG (B,D,L) -> A2 (b*L+l, [hi|lo]) via 32x32 smem transpose; d restricted to a half
__global__ void yg_convert_kernel(const float* __restrict__ YG, __nv_bfloat16* __restrict__ A2,
                                  int d0off)
{
    __shared__ float tile[32][33];
    const int b = blockIdx.z;
    const int d0 = d0off + blockIdx.y * 32;
    const int l0 = blockIdx.x * 32;
    const int tx = threadIdx.x, ty = threadIdx.y;
    for (int i = ty; i < 32; i += 8)
        tile[i][tx] = YG[((size_t)b * DMOD + d0 + i) * LSEQ + l0 + tx];
    __syncthreads();
    for (int i = ty; i < 32; i += 8) {
        float v = tile[tx][i];
        __nv_bfloat16 h = __float2bfloat16(v);
        __nv_bfloat16 l = __float2bfloat16(v - __bfloat162float(h));
        size_t m = (size_t)b * LSEQ + l0 + i;
        A2[m * KPACK + d0 + tx]        = h;
        A2[m * KPACK + 2048 + d0 + tx] = l;
    }
}

// ---------------- shared GEMM building blocks ----------------
__device__ __forceinline__ void load_stage(uint32_t sA, uint32_t sB,
                                           const __nv_bfloat16* __restrict__ A,
                                           const __nv_bfloat16* __restrict__ Bm,
                                           int m0, int n0, int kA, int kB, int tid)
{
#pragma unroll
    for (int i = 0; i < 8; ++i) {
        int g = tid + i * GEMM_T;
        int row = g >> 3, seg = g & 7;
        const void* gp = A + (size_t)(m0 + row) * KPACK + kA + seg * 8;
        uint32_t off = (uint32_t)(row * 128 + seg * 16);
        CP_ASYNC16(sA + SWZ(off), gp);
    }
#pragma unroll
    for (int i = 0; i < 8; ++i) {
        int g = tid + i * GEMM_T;
        int row = g >> 3, seg = g & 7;
        const void* gp = Bm + (size_t)(n0 + row) * KPACK + kB + seg * 8;
        uint32_t off = (uint32_t)(row * 128 + seg * 16);
        CP_ASYNC16(sB + SWZ(off), gp);
    }
}

__device__ __forceinline__ void compute_chunk(uint32_t sA, uint32_t sB,
                                              int lane, int wm, int wn,
                                              float acc[4][8][4])
{
    const int rlow = lane & 15;
    const int khalf = (lane >> 4) * 16;
#pragma unroll
    for (int kk = 0; kk < 4; ++kk) {
        const int kb = kk * 32 + khalf;
        uint32_t af[4][4], bf[8][2];
#pragma unroll
        for (int mt = 0; mt < 4; ++mt) {
            uint32_t off = (uint32_t)((wm * 64 + mt * 16 + rlow) * 128 + kb);
            LDSM_X4(af[mt][0], af[mt][1], af[mt][2], af[mt][3], sA + SWZ(off));
        }
#pragma unroll
        for (int nb = 0; nb < 4; ++nb) {
            uint32_t r0, r1, r2, r3;
            uint32_t off = (uint32_t)((wn * 64 + nb * 16 + rlow) * 128 + kb);
            LDSM_X4(r0, r1, r2, r3, sB + SWZ(off));
            bf[nb * 2][0] = r0; bf[nb * 2][1] = r2;
            bf[nb * 2 + 1][0] = r1; bf[nb * 2 + 1][1] = r3;
        }
#pragma unroll
        for (int mt = 0; mt < 4; ++mt)
#pragma unroll
            for (int nf = 0; nf < 8; ++nf)
                MMA16816(acc[mt][nf], af[mt], bf[nf]);
    }
}

// full-K maps (gemm1): A {hi,lo,hi}, B {hi,hi,lo} over packed [hi|lo]
__device__ __forceinline__ int mapA(int k0) { int s = k0 >> 11; return ((s & 1) << 11) + (k0 & 2047); }
__device__ __forceinline__ int mapB(int k0) { int s = k0 >> 11; return ((s >> 1) << 11) + (k0 & 2047); }
// half-K maps (gemm2): k0 in [0, 3072), half h
__device__ __forceinline__ int mapA2(int k0, int h) {
    int s = k0 >> 10, w = k0 & 1023;
    return ((s & 1) << 11) + (h << 10) + w;
}
__device__ __forceinline__ int mapB2(int k0, int h) {
    int s = k0 >> 10, w = k0 & 1023;
    return ((s >> 1) << 11) + (h << 10) + w;
}

// ---------------- gemm1: full K, transposed store into U (B,3D,L) ----------------
__global__ __launch_bounds__(GEMM_T, 2) void gemm1_kernel(
    const __nv_bfloat16* __restrict__ A, const __nv_bfloat16* __restrict__ Bm,
    const float* __restrict__ bias, float* __restrict__ out, int Ntot)
{
    extern __shared__ char smem[];
    const uint32_t sbase = smem_to_u32(smem);
    const int tid = threadIdx.x;
    const int lane = tid & 31, wid = tid >> 5;
    const int wm = wid >> 1, wn = wid & 1;

    int bid = blockIdx.y * gridDim.x + blockIdx.x;
    int per = SUPER_M * gridDim.x;
    int sup = bid / per, rem = bid % per;
    const int m0 = (sup * SUPER_M + (rem & (SUPER_M - 1))) * BM;
    const int n0 = (rem / SUPER_M) * BN;

    float acc[4][8][4];
#pragma unroll
    for (int a = 0; a < 4; ++a)
#pragma unroll
        for (int b = 0; b < 8; ++b)
#pragma unroll
            for (int c = 0; c < 4; ++c) acc[a][b][c] = 0.f;

    load_stage(sbase, sbase + 16384, A, Bm, m0, n0, mapA(0), mapB(0), tid);
    CP_COMMIT();
    load_stage(sbase + STAGE, sbase + STAGE + 16384, A, Bm, m0, n0, mapA(BK), mapB(BK), tid);
    CP_COMMIT();

    for (int c = 0; c < NCHUNK; ++c) {
        CP_WAIT1();
        __syncthreads();
        if (c + 2 < NCHUNK) {
            int st = (c + 2) % NSTAGE;
            int k0 = (c + 2) * BK;
            load_stage(sbase + st * STAGE, sbase + st * STAGE + 16384,
                       A, Bm, m0, n0, mapA(k0), mapB(k0), tid);
        }
        CP_COMMIT();
        int st = c % NSTAGE;
        compute_chunk(sbase + st * STAGE, sbase + st * STAGE + 16384, lane, wm, wn, acc);
    }
    __syncthreads();

    float (*sc)[132] = (float(*)[132])smem;
#pragma unroll
    for (int mt = 0; mt < 4; ++mt) {
        int ml = wm * 64 + mt * 16 + (lane >> 2);
#pragma unroll
        for (int nf = 0; nf < 8; ++nf) {
            int nl = wn * 64 + nf * 8 + (lane & 3) * 2;
            sc[nl][ml]         = acc[mt][nf][0];
            sc[nl + 1][ml]     = acc[mt][nf][1];
            sc[nl][ml + 8]     = acc[mt][nf][2];
            sc[nl + 1][ml + 8] = acc[mt][nf][3];
        }
    }
    __syncthreads();
    const int b = m0 >> 12;
    const int lbase = m0 & (LSEQ - 1);
    const int n = tid;
    const float bb = bias[n0 + n];
    float* dst = out + ((size_t)b * D3 + n0 + n) * LSEQ + lbase;
    const float* srow = &sc[n][0];
#pragma unroll
    for (int i = 0; i < 32; ++i) {
        float4 v = *(const float4*)(srow + i * 4);
        v.x += bb; v.y += bb; v.z += bb; v.w += bb;
        *(float4*)(dst + i * 4) = v;
    }
}

// ---------------- gemm2: half-K passes. PASS 0: out = acc + bias. PASS 1: out += acc ----
template <int PASS>
__global__ __launch_bounds__(GEMM_T, 2) void gemm2_kernel(
    const __nv_bfloat16* __restrict__ A, const __nv_bfloat16* __restrict__ Bm,
    const float* __restrict__ bias, float* __restrict__ out, int Ntot)
{
    extern __shared__ char smem[];
    const uint32_t sbase = smem_to_u32(smem);
    const int tid = threadIdx.x;
    const int lane = tid & 31, wid = tid >> 5;
    const int wm = wid >> 1, wn = wid & 1;

    int bid = blockIdx.y * gridDim.x + blockIdx.x;
    int per = SUPER_M * gridDim.x;
    int sup = bid / per, rem = bid % per;
    const int m0 = (sup * SUPER_M + (rem & (SUPER_M - 1))) * BM;
    const int n0 = (rem / SUPER_M) * BN;

    float acc[4][8][4];
#pragma unroll
    for (int a = 0; a < 4; ++a)
#pragma unroll
        for (int b = 0; b < 8; ++b)
#pragma unroll
            for (int c = 0; c < 4; ++c) acc[a][b][c] = 0.f;

    load_stage(sbase, sbase + 16384, A, Bm, m0, n0, mapA2(0, PASS), mapB2(0, PASS), tid);
    CP_COMMIT();
    load_stage(sbase + STAGE, sbase + STAGE + 16384, A, Bm, m0, n0,
               mapA2(BK, PASS), mapB2(BK, PASS), tid);
    CP_COMMIT();

    for (int c = 0; c < NCHUNK2; ++c) {
        CP_WAIT1();
        __syncthreads();
        if (c + 2 < NCHUNK2) {
            int st = (c + 2) % NSTAGE;
            int k0 = (c + 2) * BK;
            load_stage(sbase + st * STAGE, sbase + st * STAGE + 16384,
                       A, Bm, m0, n0, mapA2(k0, PASS), mapB2(k0, PASS), tid);
        }
        CP_COMMIT();
        int st = c % NSTAGE;
        compute_chunk(sbase + st * STAGE, sbase + st * STAGE + 16384, lane, wm, wn, acc);
    }
    __syncthreads();

    const int mw = m0 + wm * 64, nw = n0 + wn * 64;
#pragma unroll
    for (int mt = 0; mt < 4; ++mt) {
        int row = mw + mt * 16 + (lane >> 2);
#pragma unroll
        for (int nf = 0; nf < 8; ++nf) {
            int col = nw + nf * 8 + (lane & 3) * 2;
            float2 v0, v1;
            if (PASS == 0) {
                float b0v = bias[col], b1v = bias[col + 1];
                v0 = make_float2(acc[mt][nf][0] + b0v, acc[mt][nf][1] + b1v);
                v1 = make_float2(acc[mt][nf][2] + b0v, acc[mt][nf][3] + b1v);
            } else {
                float2 o0 = *(const float2*)&out[(size_t)row * Ntot + col];
                float2 o1 = *(const float2*)&out[(size_t)(row + 8) * Ntot + col];
                v0 = make_float2(acc[mt][nf][0] + o0.x, acc[mt][nf][1] + o0.y);
                v1 = make_float2(acc[mt][nf][2] + o1.x, acc[mt][nf][3] + o1.y);
            }
            *(float2*)&out[(size_t)row * Ntot + col] = v0;
            *(float2*)&out[(size_t)(row + 8) * Ntot + col] = v1;
        }
    }
}

// ---------------- twiddle init ----------------
__global__ void twiddle_kernel() {
    int j = blockIdx.x * blockDim.x + threadIdx.x;
    if (j < FFT_HN) {
        double s, c;
        sincospi(-2.0 * (double)j / (double)FFT_N, &s, &c);
        g_TW[j] = make_float2((float)c, (float)s);
    }
}

// ---------------- radix-4 FFT (N=8192 = 2 * 4^6, 512 threads) ----------------
__device__ __forceinline__ void fft_fwd4(float2* z) {
#pragma unroll
    for (int r = 0; r < 8; ++r) {
        int t = threadIdx.x + r * FFT_T;
        float2 a = z[t], b = z[t + 4096];
        z[t] = cadd(a, b);
        z[t + 4096] = cmul(csub(a, b), g_TW[t]);
    }
    __syncthreads();
#pragma unroll
    for (int n = 4096; n >= 4; n >>= 2) {
        const int q = n >> 2;
        const int s = FFT_N / n;
#pragma unroll
        for (int r = 0; r < 4; ++r) {
            int t = threadIdx.x + r * FFT_T;
            int j = t & (q - 1);
            int base = ((t / q) * n) + j;
            float2 a0 = z[base], a1 = z[base + q], a2 = z[base + 2 * q], a3 = z[base + 3 * q];
            float2 t0 = cadd(a0, a2), t2 = csub(a0, a2);
            float2 t1 = cadd(a1, a3);
            float2 d13 = csub(a1, a3);
            float2 t3 = make_float2(d13.y, -d13.x);
            float2 w1 = g_TW[j * s], w2 = g_TW[2 * j * s];
            float2 w3 = cmul(w1, w2);
            z[base]         = cadd(t0, t1);
            z[base + q]     = cmul(cadd(t2, t3), w1);
            z[base + 2 * q] = cmul(csub(t0, t1), w2);
            z[base + 3 * q] = cmul(csub(t2, t3), w3);
        }
        __syncthreads();
    }
}
__device__ __forceinline__ void fft_inv4(float2* z) {
#pragma unroll
    for (int n = 4; n <= 4096; n <<= 2) {
        const int q = n >> 2;
        const int s = FFT_N / n;
#pragma unroll
        for (int r = 0; r < 4; ++r) {
            int t = threadIdx.x + r * FFT_T;
            int j = t & (q - 1);
            int base = ((t / q) * n) + j;
            float2 w1 = g_TW[j * s], w2 = g_TW[2 * j * s];
            float2 w3 = cmul(w1, w2);
            float2 c0 = z[base];
            float2 c1 = cmulc(z[base + q], w1);
            float2 c2 = cmulc(z[base + 2 * q], w2);
            float2 c3 = cmulc(z[base + 3 * q], w3);
            float2 s02 = cadd(c0, c2), d02 = csub(c0, c2);
            float2 s13 = cadd(c1, c3), d13 = csub(c1, c3);
            float2 id13 = make_float2(-d13.y, d13.x);
            z[base]         = cadd(s02, s13);
            z[base + q]     = cadd(d02, id13);
            z[base + 2 * q] = csub(s02, s13);
            z[base + 3 * q] = csub(d02, id13);
        }
        __syncthreads();
    }
#pragma unroll
    for (int r = 0; r < 8; ++r) {
        int t = threadIdx.x + r * FFT_T;
        float2 c0 = z[t];
        float2 c1 = cmulc(z[t + 4096], g_TW[t]);
        z[t] = cadd(c0, c1);
        z[t + 4096] = csub(c0, c1);
    }
    __syncthreads();
}

// ---------------- filter MLP ----------------
__global__ void filter_h_kernel(const float* __restrict__ w0, const float* __restrict__ b0,
                                const float* __restrict__ freq,
                                const float* __restrict__ w1, const float* __restrict__ b1,
                                const float* __restrict__ w2, const float* __restrict__ b2,
                                float* __restrict__ H)
{
    const int l = blockIdx.x;
    const int f = threadIdx.x;
    __shared__ float h1s[64];
    __shared__ float h2s[64];
    const float t  = (float)l / (float)(LSEQ - 1);
    const float ang = 1e-4f * 2.0f * 3.14159265358979323846f * (float)l / (float)LSEQ;
    const float z0 = t, z1 = cosf(ang), z2 = -sinf(ang);
    const float fr = freq[f];
    float pre = z0 * w0[f * 3 + 0] + z1 * w0[f * 3 + 1] + z2 * w0[f * 3 + 2] + b0[f];
    h1s[f] = sinf(fr * pre);
    __syncthreads();
    float s = b1[f];
#pragma unroll
    for (int g = 0; g < 64; ++g) s = fmaf(h1s[g], w1[f * 64 + g], s);
    h2s[f] = sinf(fr * s);
    __syncthreads();
    s = b2[f];
#pragma unroll
    for (int g = 0; g < 64; ++g) s = fmaf(h2s[g], w2[f * 64 + g], s);
    H[(size_t)l * 64 + f] = sinf(fr * s);
}

// ---------------- K_time ----------------
__global__ __launch_bounds__(128) void ktime_kernel(const float* __restrict__ H,
                                                    const float* __restrict__ w3,
                                                    float* __restrict__ Kt)
{
    __shared__ float Hs[128][65];
    __shared__ float w3s[16][64];
    const int l0 = blockIdx.x * 128;
    const int d0 = blockIdx.y * 16;
    const int tid = threadIdx.x;
    for (int idx = tid; idx < 128 * 64; idx += 128)
        Hs[idx >> 6][idx & 63] = H[(size_t)(l0 + (idx >> 6)) * 64 + (idx & 63)];
    for (int idx = tid; idx < 16 * 64; idx += 128)
        w3s[idx >> 6][idx & 63] = w3[(size_t)(d0 + (idx >> 6)) * 64 + (idx & 63)];
    __syncthreads();
    const int l = l0 + tid;
    const float t = (float)l / (float)(LSEQ - 1);
    const float MIND = -3.0701134573253943f;
    const float MAXD = -15.350567286626971f;
#pragma unroll 4
    for (int dd = 0; dd < 16; ++dd) {
        int d = d0 + dd;
        float delta = MIND + (MAXD - MIND) * ((float)d / 2047.0f);
        float decay = expf(t * delta);
        float s = 0.f;
#pragma unroll
        for (int f = 0; f < 64; ++f) s = fmaf(Hs[tid][f], w3s[dd][f], s);
        Kt[(size_t)d * LSEQ + l] = s * decay;
    }
}

// ---------------- FFT of filter ----------------
__global__ __launch_bounds__(FFT_T) void fftk_kernel(const float* __restrict__ Kt,
                                                     float2* __restrict__ Kf)
{
    extern __shared__ float2 zf[];
    const int d = blockIdx.x;
    const float* src = &Kt[(size_t)d * LSEQ];
    for (int t = threadIdx.x; t < FFT_N; t += FFT_T)
        zf[t] = make_float2((t < LSEQ) ? src[t] : 0.f, 0.f);
    __syncthreads();
    fft_fwd4(zf);
    float2* dst = &Kf[(size_t)d * FFT_N];
    for (int t = threadIdx.x; t < FFT_N; t += FFT_T) dst[t] = zf[t];
}

// ---------------- fused short-conv + FFT conv + gate (d-half; vg register-cached) ------
__global__ __launch_bounds__(FFT_T) void fftconv_fused_kernel(
    const float2* __restrict__ Kf, const float* __restrict__ U,
    const float* __restrict__ sw, const float* __restrict__ sb,
    const float* __restrict__ fbias, float* __restrict__ YG, int d0off)
{
    extern __shared__ float2 zf[];
    const int d = d0off + blockIdx.x;
    const int c1 = d + DMOD, c2 = d + 2 * DMOD;
    const float w00 = sw[d * 3],  w01 = sw[d * 3 + 1],  w02 = sw[d * 3 + 2],  bb0 = sb[d];
    const float w10 = sw[c1 * 3], w11 = sw[c1 * 3 + 1], w12 = sw[c1 * 3 + 2], bb1 = sb[c1];
    const float w20 = sw[c2 * 3], w21 = sw[c2 * 3 + 1], w22 = sw[c2 * 3 + 2], bb2 = sb[c2];

    const float* u1b0 = &U[((size_t)0 * D3 + c1) * LSEQ];
    const float* u2b0 = &U[((size_t)0 * D3 + c2) * LSEQ];
    const float* u1b1 = &U[((size_t)1 * D3 + c1) * LSEQ];
    const float* u2b1 = &U[((size_t)1 * D3 + c2) * LSEQ];

    float2 vg[8];   // cached (vg_b0, vg_b1) per l-slot — reused in epilogue
#pragma unroll
    for (int r = 0; r < 8; ++r) {
        int l = threadIdx.x + r * FFT_T;
        float a2_0 = (l >= 2) ? u1b0[l - 2] : 0.f;
        float a1_0 = (l >= 1) ? u1b0[l - 1] : 0.f;
        float b2_0 = (l >= 2) ? u2b0[l - 2] : 0.f;
        float b1_0 = (l >= 1) ? u2b0[l - 1] : 0.f;
        float x1_0 = fmaf(w10, a2_0, fmaf(w11, a1_0, fmaf(w12, u1b0[l], bb1)));
        float v_0  = fmaf(w20, b2_0, fmaf(w21, b1_0, fmaf(w22, u2b0[l], bb2)));
        float a2_1 = (l >= 2) ? u1b1[l - 2] : 0.f;
        float a1_1 = (l >= 1) ? u1b1[l - 1] : 0.f;
        float b2_1 = (l >= 2) ? u2b1[l - 2] : 0.f;
        float b1_1 = (l >= 1) ? u2b1[l - 1] : 0.f;
        float x1_1 = fmaf(w10, a2_1, fmaf(w11, a1_1, fmaf(w12, u1b1[l], bb1)));
        float v_1  = fmaf(w20, b2_1, fmaf(w21, b1_1, fmaf(w22, u2b1[l], bb2)));
        vg[r] = make_float2(v_0 * x1_0, v_1 * x1_1);
        zf[l] = vg[r];
    }
#pragma unroll
    for (int r = 0; r < 8; ++r)
        zf[threadIdx.x + LSEQ + r * FFT_T] = make_float2(0.f, 0.f);
    __syncthreads();
    fft_fwd4(zf);
    const float2* kf = &Kf[(size_t)d * FFT_N];
    for (int t = threadIdx.x; t < FFT_N; t += FFT_T)
        zf[t] = cmul(zf[t], kf[t]);
    __syncthreads();
    fft_inv4(zf);

    const float bb = fbias[d];
    const float* u0b0 = &U[((size_t)0 * D3 + d) * LSEQ];
    const float* u0b1 = &U[((size_t)1 * D3 + d) * LSEQ];
    float* y0 = &YG[(size_t)d * LSEQ];
    float* y1 = &YG[((size_t)DMOD + d) * LSEQ];
    const float inv = 1.0f / (float)FFT_N;
#pragma unroll
    for (int r = 0; r < 8; ++r) {
        int l = threadIdx.x + r * FFT_T;
        float c2_0 = (l >= 2) ? u0b0[l - 2] : 0.f;
        float c1_0 = (l >= 1) ? u0b0[l - 1] : 0.f;
        float x0_0 = fmaf(w00, c2_0, fmaf(w01, c1_0, fmaf(w02, u0b0[l], bb0)));
        float c2_1 = (l >= 2) ? u0b1[l - 2] : 0.f;
        float c1_1 = (l >= 1) ? u0b1[l - 1] : 0.f;
        float x0_1 = fmaf(w00, c2_1, fmaf(w01, c1_1, fmaf(w02, u0b1[l], bb0)));
        float2 yv = zf[l];
        y0[l] = fmaf(yv.x, inv, bb * vg[r].x) * x0_0;
        y1[l] = fmaf(yv.y, inv, bb * vg[r].y) * x0_1;
    }
}

// ---------------- launch ----------------
extern "C" void kernel_launch(void* const* d_in, const int* in_sizes, int n_in,
                              void* d_out, int out_size)
{
    const float* x        = (const float*)d_in[0];
    const float* in_w     = (const float*)d_in[1];
    const float* in_b     = (const float*)d_in[2];
    const float* short_w  = (const float*)d_in[3];
    const float* short_b  = (const float*)d_in[4];
    const float* mlp_w0   = (const float*)d_in[5];
    const float* mlp_b0   = (const float*)d_in[6];
    const float* sin_freq = (const float*)d_in[7];
    const float* mlp_w1   = (const float*)d_in[8];
    const float* mlp_b1   = (const float*)d_in[9];
    const float* mlp_w2   = (const float*)d_in[10];
    const float* mlp_b2   = (const float*)d_in[11];
    const float* mlp_w3   = (const float*)d_in[12];
    const float* f_bias   = (const float*)d_in[13];
    const float* out_w    = (const float*)d_in[14];
    const float* out_b    = (const float*)d_in[15];
    float* out = (float*)d_out;

    cudaFuncSetAttribute(fftk_kernel, cudaFuncAttributeMaxDynamicSharedMemorySize, FFT_N * 8);
    cudaFuncSetAttribute(fftconv_fused_kernel, cudaFuncAttributeMaxDynamicSharedMemorySize, FFT_N * 8);
    cudaFuncSetAttribute(gemm1_kernel, cudaFuncAttributeMaxDynamicSharedMemorySize, GEMM_SMEM);
    cudaFuncSetAttribute(gemm2_kernel<0>, cudaFuncAttributeMaxDynamicSharedMemorySize, GEMM_SMEM);
    cudaFuncSetAttribute(gemm2_kernel<1>, cudaFuncAttributeMaxDynamicSharedMemorySize, GEMM_SMEM);

    float* U;   cudaGetSymbolAddress((void**)&U,   g_U);
    float* H;   cudaGetSymbolAddress((void**)&H,   g_H);
    float* Kt;  cudaGetSymbolAddress((void**)&Kt,  g_Kt);
    float2* Kf; cudaGetSymbolAddress((void**)&Kf,  g_Kf);
    float* YG;  cudaGetSymbolAddress((void**)&YG,  g_YG);
    __nv_bfloat16* A1; cudaGetSymbolAddress((void**)&A1, g_A1);
    __nv_bfloat16* B1; cudaGetSymbolAddress((void**)&B1, g_B1);
    __nv_bfloat16* B2; cudaGetSymbolAddress((void**)&B2, g_B2);
    __nv_bfloat16* A2; cudaGetSymbolAddress((void**)&A2, g_A2);

    // Side stream + events, created ONCE during the (uncaptured) correctness call.
    static cudaStream_t s_side = nullptr;
    static cudaEvent_t s_fork = nullptr, s_evF = nullptr, s_evH0 = nullptr, s_evS = nullptr;
    if (s_side == nullptr) {
        cudaStreamCreateWithFlags(&s_side, cudaStreamNonBlocking);
        cudaEventCreateWithFlags(&s_fork, cudaEventDisableTiming);
        cudaEventCreateWithFlags(&s_evF, cudaEventDisableTiming);
        cudaEventCreateWithFlags(&s_evH0, cudaEventDisableTiming);
        cudaEventCreateWithFlags(&s_evS, cudaEventDisableTiming);
    }

    // ---- fork ----
    cudaEventRecord(s_fork, 0);
    cudaStreamWaitEvent(s_side, s_fork, 0);

    // main: operand converts + gemm1
    {
        size_t t4 = (size_t)BATCH * LSEQ * DMOD / 4;
        convert_split_kernel<<<(unsigned)((t4 + 255) / 256), 256>>>(x, A1, t4);
        t4 = (size_t)D3 * DMOD / 4;
        convert_split_kernel<<<(unsigned)((t4 + 255) / 256), 256>>>(in_w, B1, t4);
    }
    gemm1_kernel<<<dim3(D3 / BN, (BATCH * LSEQ) / BM), GEMM_T, GEMM_SMEM>>>(
        A1, B1, in_b, U, D3);

    // side: filter path + out_proj weight convert (hidden under gemm1)
    twiddle_kernel<<<16, 256, 0, s_side>>>();
    filter_h_kernel<<<LSEQ, 64, 0, s_side>>>(mlp_w0, mlp_b0, sin_freq,
                                             mlp_w1, mlp_b1, mlp_w2, mlp_b2, H);
    ktime_kernel<<<dim3(LSEQ / 128, DMOD / 16), 128, 0, s_side>>>(H, mlp_w3, Kt);
    fftk_kernel<<<DMOD, FFT_T, FFT_N * 8, s_side>>>(Kt, Kf);
    {
        size_t t4 = (size_t)DMOD * DMOD / 4;
        convert_split_kernel<<<(unsigned)((t4 + 255) / 256), 256, 0, s_side>>>(out_w, B2, t4);
    }
    cudaEventRecord(s_evF, s_side);

    // main: wait filter path -> fftconv half0 -> ygc half0 -> gemm2 pass A
    cudaStreamWaitEvent(0, s_evF, 0);
    fftconv_fused_kernel<<<DHALF, FFT_T, FFT_N * 8>>>(Kf, U, short_w, short_b, f_bias, YG, 0);
    cudaEventRecord(s_evH0, 0);
    yg_convert_kernel<<<dim3(LSEQ / 32, DHALF / 32, BATCH), dim3(32, 8)>>>(YG, A2, 0);
    gemm2_kernel<0><<<dim3(DMOD / BN, (BATCH * LSEQ) / BM), GEMM_T, GEMM_SMEM>>>(
        A2, B2, out_b, out, DMOD);

    // side: half1 runs under gemm2 pass A
    cudaStreamWaitEvent(s_side, s_evH0, 0);
    fftconv_fused_kernel<<<DHALF, FFT_T, FFT_N * 8, s_side>>>(Kf, U, short_w, short_b,
                                                              f_bias, YG, DHALF);
    yg_convert_kernel<<<dim3(LSEQ / 32, DHALF / 32, BATCH), dim3(32, 8), 0, s_side>>>(
        YG, A2, DHALF);
    cudaEventRecord(s_evS, s_side);

    // main: join -> gemm2 pass B (accumulates into out)
    cudaStreamWaitEvent(0, s_evS, 0);
    gemm2_kernel<1><<<dim3(DMOD / BN, (BATCH * LSEQ) / BM), GEMM_T, GEMM_SMEM>>>(
        A2, B2, out_b, out, DMOD);
}